// round 14
// baseline (speedup 1.0000x reference)
#include <cuda_runtime.h>
#include <cuda_bf16.h>
#include <math.h>
#include <stdint.h>

constexpr int kB = 128, kH = 512, kCtx = 365, kPred = 90, kT = 455;
constexpr int kDdyn = 10, kEmb = 64, kStat = 36, kMlp = 128, kOut = 4;
constexpr int kNG = 2048, kNCTA = 128, kNTls = 32, kKS = 4;
constexpr int kAW0 = 256, kAW1 = 512;            // activation row words (packed bf16 pairs)
constexpr int kHid = 256, kM2 = kPred * kB;
// SMEM word offsets
constexpr int oW0h = 0, oW0l = 4352, oW1h = 8704, oW1l = 17152;   // W0:64x68, W1:64x132
constexpr int oWd = 25600;                        // f32 [10][64]
constexpr int oAh = 26240, oAl = 40064;           // ring: 3 x 128 x 36 words each
constexpr int kSmemBytes = 53888 * 4;             // 215552

__device__ float g_pre0[kB * kNG];
__device__ float g_pre1[kNG];
__device__ __align__(16) uint32_t g_h0h[2 * kB * kAW0];
__device__ __align__(16) uint32_t g_h0l[2 * kB * kAW0];
__device__ __align__(16) uint32_t g_i1h[2 * kB * kAW1];
__device__ __align__(16) uint32_t g_i1l[2 * kB * kAW1];
__device__ float g_c0[kB * kH];
__device__ float g_c1[kB * kH];
__device__ float g_emb[kB * kEmb];
__device__ float g_mlp1[kB * kMlp];
__device__ __align__(16) float g_part[2 * kNCTA * kB * 64];   // per-layer planes
__device__ unsigned g_cnt0[kNTls], g_cnt1[kNTls];             // monotonic handoff
__device__ unsigned g_d0, g_d1;                               // monotonic done counters
__device__ unsigned g_gen, g_barcnt;                          // one-shot gridbar
__device__ __align__(16) float g_Y1[kM2 * kH];
__device__ __align__(16) float g_hid[kM2 * kHid];

__device__ __forceinline__ float sigm(float x) { return 1.f / (1.f + expf(-x)); }

__device__ __forceinline__ void split2(float e0, float e1, uint32_t& hi, uint32_t& lo) {
    float h0 = __bfloat162float(__float2bfloat16(e0));
    float h1 = __bfloat162float(__float2bfloat16(e1));
    asm("cvt.rn.bf16x2.f32 %0, %1, %2;" : "=r"(hi) : "f"(h1), "f"(h0));
    asm("cvt.rn.bf16x2.f32 %0, %1, %2;" : "=r"(lo) : "f"(e1 - h1), "f"(e0 - h0));
}

__device__ __forceinline__ void mma16(float c[4], const uint32_t a[4], uint32_t b0, uint32_t b1) {
    asm volatile("mma.sync.aligned.m16n8k16.row.col.f32.bf16.bf16.f32 "
                 "{%0,%1,%2,%3},{%4,%5,%6,%7},{%8,%9},{%0,%1,%2,%3};\n"
                 : "+f"(c[0]), "+f"(c[1]), "+f"(c[2]), "+f"(c[3])
                 : "r"(a[0]), "r"(a[1]), "r"(a[2]), "r"(a[3]), "r"(b0), "r"(b1));
}

__device__ __forceinline__ void cpa16(void* sptr, const void* gptr) {
    uint32_t s = (uint32_t)__cvta_generic_to_shared(sptr);
    asm volatile("cp.async.cg.shared.global [%0], [%1], 16;\n" :: "r"(s), "l"(gptr));
}

__device__ __forceinline__ void gridbar(unsigned& bt) {
    __threadfence();
    __syncthreads();
    if (threadIdx.x == 0) {
        unsigned arr = atomicAdd(&g_barcnt, 1u);
        if ((arr & (kNCTA - 1)) == kNCTA - 1) {
            asm volatile("st.release.gpu.global.u32 [%0], %1;" :: "l"(&g_gen), "r"(bt));
        } else {
            unsigned v;
            do { asm volatile("ld.acquire.gpu.global.u32 %0, [%1];" : "=r"(v) : "l"(&g_gen)); }
            while ((int)(v - bt) < 0);
        }
    }
    __syncthreads();
    bt++;
}

__device__ __forceinline__ void spinw(unsigned* p, unsigned tgt) {
    if (threadIdx.x == 0) {
        unsigned v;
        do { asm volatile("ld.acquire.gpu.global.u32 %0, [%1];" : "=r"(v) : "l"(p)); }
        while ((int)(v - tgt) < 0);
    }
    __syncthreads();
}

// ---------------- prep (5 launches) ----------------
__global__ void prep_mlp1(const float* __restrict__ sx, const float* __restrict__ w1,
                          const float* __restrict__ b1) {
    int b = blockIdx.x, m = threadIdx.x;
    float s = b1[m];
    #pragma unroll
    for (int d = 0; d < kStat; d++) s += sx[b * kStat + d] * w1[m * kStat + d];
    g_mlp1[b * kMlp + m] = fmaxf(s, 0.f);
}
__global__ void prep_emb(const float* __restrict__ sx, const float* __restrict__ ew,
                         const float* __restrict__ eb) {
    int b = blockIdx.x, e = threadIdx.x;
    float s = eb[e];
    #pragma unroll
    for (int d = 0; d < kStat; d++) s += sx[b * kStat + d] * ew[e * kStat + d];
    g_emb[b * kEmb + e] = fmaxf(s, 0.f);
}
__global__ void prep_init(const float* __restrict__ w2, const float* __restrict__ b2) {
    int b = blockIdx.x;
    int r = 2 * (blockIdx.y * 256 + threadIdx.x);
    float s0 = b2[r], s1 = b2[r + 1];
    #pragma unroll 4
    for (int m = 0; m < kMlp; m++) {
        float a = g_mlp1[b * kMlp + m];
        s0 += a * w2[r * kMlp + m];
        s1 += a * w2[(r + 1) * kMlp + m];
    }
    int ss = r >> 10, l = (r >> 9) & 1, h = r & 511;
    if (ss == 0) {
        uint32_t hi, lo; split2(s0, s1, hi, lo);
        int w = h >> 1;
        if (l == 0) { g_h0h[b * kAW0 + w] = hi; g_h0l[b * kAW0 + w] = lo; }
        else        { g_i1h[b * kAW1 + 256 + w] = hi; g_i1l[b * kAW1 + 256 + w] = lo; }
    } else {
        if (l == 0) { g_c0[b * kH + h] = s0; g_c0[b * kH + h + 1] = s1; }
        else        { g_c1[b * kH + h] = s0; g_c1[b * kH + h + 1] = s1; }
    }
}
__global__ void prep_pre0(const float* __restrict__ wih0, const float* __restrict__ bih,
                          const float* __restrict__ bhh) {
    int b = blockIdx.x;
    int n = blockIdx.y * 256 + threadIdx.x;
    int j = (n & 3) * kH + (n >> 2);
    float s = bih[j] + bhh[j];
    #pragma unroll 8
    for (int e = 0; e < kEmb; e++)
        s += g_emb[b * kEmb + e] * wih0[j * (kDdyn + kEmb) + kDdyn + e];
    g_pre0[b * kNG + n] = s;
}
__global__ void prep_pre1(const float* __restrict__ bih, const float* __restrict__ bhh) {
    int n = blockIdx.x * 256 + threadIdx.x;
    int j = (n & 3) * kH + (n >> 2);
    g_pre1[n] = bih[j] + bhh[j];
}

// ---------------- GEMM phase: K=64/iter, 3-buf ring, 1 sync/iter ----------------
template <int NIT, int BSTR>
__device__ __forceinline__ void gemm_phase(
    const uint32_t* __restrict__ gAh, const uint32_t* __restrict__ gAl, int astrw, int kwb,
    const uint32_t* __restrict__ Bh, const uint32_t* __restrict__ Bl,
    uint32_t* __restrict__ Ah, uint32_t* __restrict__ Al,
    int tid, int wm, int wn, int g, int t4, float acc[2][4][4])
{
    auto stage = [&](int buf, int c) {
        int kw0 = kwb + c * 32;
        #pragma unroll
        for (int q = 0; q < 4; q++) {
            int seg = tid * 4 + q;                // 1024 segs: 128 rows x 8 x 16B
            int row = seg >> 3, sc = seg & 7;
            cpa16(Ah + buf * 4608 + row * 36 + sc * 4, gAh + row * astrw + kw0 + sc * 4);
            cpa16(Al + buf * 4608 + row * 36 + sc * 4, gAl + row * astrw + kw0 + sc * 4);
        }
        asm volatile("cp.async.commit_group;\n");
    };
    auto compute = [&](int buf, int j) {
        const uint32_t* AhB = Ah + buf * 4608;
        const uint32_t* AlB = Al + buf * 4608;
        const int kb = j * 32;
        #pragma unroll
        for (int s = 0; s < 4; s++) {
            int cw = s * 8;
            uint32_t ah[2][4], al[2][4];
            #pragma unroll
            for (int mf = 0; mf < 2; mf++) {
                int r0 = (wm * 32 + mf * 16 + g) * 36 + cw;
                int r1 = r0 + 8 * 36;
                ah[mf][0] = AhB[r0 + t4];     ah[mf][1] = AhB[r1 + t4];
                ah[mf][2] = AhB[r0 + 4 + t4]; ah[mf][3] = AhB[r1 + 4 + t4];
                al[mf][0] = AlB[r0 + t4];     al[mf][1] = AlB[r1 + t4];
                al[mf][2] = AlB[r0 + 4 + t4]; al[mf][3] = AlB[r1 + 4 + t4];
            }
            #pragma unroll
            for (int nf = 0; nf < 4; nf++) {
                int base = (wn * 32 + nf * 8 + g) * BSTR + kb + cw;
                uint32_t bh0 = Bh[base + t4], bh1 = Bh[base + 4 + t4];
                uint32_t bl0 = Bl[base + t4], bl1 = Bl[base + 4 + t4];
                #pragma unroll
                for (int mf = 0; mf < 2; mf++) {
                    mma16(acc[mf][nf], ah[mf], bh0, bh1);
                    mma16(acc[mf][nf], ah[mf], bl0, bl1);
                    mma16(acc[mf][nf], al[mf], bh0, bh1);
                }
            }
        }
    };
    stage(0, 0);
    if (NIT > 1) stage(1, 1);
    #pragma unroll 1
    for (int j = 0; j < NIT; j++) {
        if (j + 1 < NIT) { asm volatile("cp.async.wait_group 1;\n"); }
        else             { asm volatile("cp.async.wait_group 0;\n"); }
        __syncthreads();
        if (j + 2 < NIT) stage((j + 2) % 3, j + 2);
        compute(j % 3, j);
    }
}

// ---------------- K-split reduce + fused LSTM epilogue ----------------
template <int L>
__device__ __forceinline__ void epilogue(int par, int step, int ntile, int n0, int tid,
                                         const float* sWd,
                                         const float* __restrict__ ctx,
                                         const float* __restrict__ fut) {
    int m = tid >> 1, nh = (tid & 1) * 32;
    float s[32];
    #pragma unroll
    for (int j = 0; j < 32; j++) s[j] = 0.f;
    #pragma unroll 1
    for (int z = 0; z < kKS; z++) {
        const float4* q = reinterpret_cast<const float4*>(
            g_part + (size_t)(L * kNCTA + ntile * kKS + z) * (kB * 64) + m * 64 + nh);
        #pragma unroll
        for (int j = 0; j < 8; j++) {
            float4 v = __ldcg(q + j);
            s[j*4] += v.x; s[j*4+1] += v.y; s[j*4+2] += v.z; s[j*4+3] += v.w;
        }
    }
    if (L == 0) {          // x-term: s[j] += sum_d x[m,d] * Wd[d][nh+j]
        const float* xp = (step < kCtx)
            ? ctx + (size_t)m * (kCtx * kDdyn) + step * kDdyn
            : fut + (size_t)m * (kPred * kDdyn) + (step - kCtx) * kDdyn;
        #pragma unroll
        for (int d = 0; d < kDdyn; d++) {
            float xv = __ldg(xp + d);
            const float4* w4 = (const float4*)(sWd + d * 64 + nh);
            #pragma unroll
            for (int q = 0; q < 8; q++) {
                float4 w = w4[q];
                s[q*4]   += xv * w.x; s[q*4+1] += xv * w.y;
                s[q*4+2] += xv * w.z; s[q*4+3] += xv * w.w;
            }
        }
    }
    const float* pre = (L == 0) ? &g_pre0[m * kNG + n0 + nh] : &g_pre1[n0 + nh];
    float* cst = (L == 0) ? g_c0 : g_c1;
    float hv[8];
    #pragma unroll
    for (int j = 0; j < 32; j += 4) {
        int u = (n0 + nh + j) >> 2;
        float gi = s[j] + pre[j], gf = s[j+1] + pre[j+1];
        float gg = s[j+2] + pre[j+2], go = s[j+3] + pre[j+3];
        float iv = sigm(gi), fv = sigm(gf), gv = tanhf(gg), ov = sigm(go);
        float c = fv * __ldcg(&cst[m * kH + u]) + iv * gv;
        cst[m * kH + u] = c;
        hv[j >> 2] = ov * tanhf(c);
    }
    int wb = (n0 + nh) >> 3;
    if (L == 0) {
        uint32_t* dhh = g_h0h + (par ^ 1) * kB * kAW0 + m * kAW0 + wb;
        uint32_t* dhl = g_h0l + (par ^ 1) * kB * kAW0 + m * kAW0 + wb;
        uint32_t* dih = g_i1h + par * kB * kAW1 + m * kAW1 + wb;
        uint32_t* dil = g_i1l + par * kB * kAW1 + m * kAW1 + wb;
        #pragma unroll
        for (int p = 0; p < 4; p++) {
            uint32_t hi, lo; split2(hv[2*p], hv[2*p+1], hi, lo);
            dhh[p] = hi; dhl[p] = lo; dih[p] = hi; dil[p] = lo;
        }
    } else {
        uint32_t* dih = g_i1h + (par ^ 1) * kB * kAW1 + m * kAW1 + 256 + wb;
        uint32_t* dil = g_i1l + (par ^ 1) * kB * kAW1 + m * kAW1 + 256 + wb;
        #pragma unroll
        for (int p = 0; p < 4; p++) {
            uint32_t hi, lo; split2(hv[2*p], hv[2*p+1], hi, lo);
            dih[p] = hi; dil[p] = lo;
        }
        int trow = step - kCtx;
        if (trow >= 0) {
            int u0 = (n0 + nh) >> 2;
            #pragma unroll
            for (int p = 0; p < 8; p++)
                g_Y1[(size_t)(trow * kB + m) * kH + u0 + p] = hv[p];
        }
    }
}

// ---------------- persistent kernel ----------------
__global__ void __launch_bounds__(256, 1) lstm_persist(
    const float* __restrict__ ctx, const float* __restrict__ fut,
    const float* __restrict__ whh0, const float* __restrict__ wih0,
    const float* __restrict__ wih1, const float* __restrict__ whh1)
{
    extern __shared__ __align__(16) uint32_t smu[];
    uint32_t* sW0h = smu + oW0h; uint32_t* sW0l = smu + oW0l;
    uint32_t* sW1h = smu + oW1h; uint32_t* sW1l = smu + oW1l;
    float* sWd = (float*)(smu + oWd);
    uint32_t* Ah = smu + oAh; uint32_t* Al = smu + oAl;
    __shared__ unsigned sFlag;

    const int tid = threadIdx.x, cta = blockIdx.x;
    const int ntile = cta >> 2, kz = cta & 3, n0 = ntile * 64;

    unsigned bt  = *((volatile unsigned*)&g_gen) + 1;
    unsigned d0b = *((volatile unsigned*)&g_d0);
    unsigned d1b = *((volatile unsigned*)&g_d1);

    // pack weight slices (bf16 hi/lo pairs)
    for (int idx = tid; idx < 64 * 64; idx += 256) {           // W0: 64n x 64 words
        int nl = idx >> 6, kw = idx & 63;
        int n = n0 + nl, j = (n & 3) * kH + (n >> 2);
        int k0 = kz * 128 + 2 * kw;
        uint32_t hi, lo;
        split2(whh0[j * kH + k0], whh0[j * kH + k0 + 1], hi, lo);
        sW0h[nl * 68 + kw] = hi; sW0l[nl * 68 + kw] = lo;
    }
    for (int idx = tid; idx < 64 * 128; idx += 256) {          // W1: 64n x 128 words
        int nl = idx >> 7, kw = idx & 127;
        int n = n0 + nl, j = (n & 3) * kH + (n >> 2);
        int k0 = kz * 256 + 2 * kw, k1 = k0 + 1;
        float v0 = (k0 < kH) ? wih1[j * kH + k0] : whh1[j * kH + k0 - kH];
        float v1 = (k1 < kH) ? wih1[j * kH + k1] : whh1[j * kH + k1 - kH];
        uint32_t hi, lo; split2(v0, v1, hi, lo);
        sW1h[nl * 132 + kw] = hi; sW1l[nl * 132 + kw] = lo;
    }
    for (int idx = tid; idx < kDdyn * 64; idx += 256) {        // Wd f32 [10][64]
        int d = idx >> 6, nl = idx & 63;
        int n = n0 + nl, j = (n & 3) * kH + (n >> 2);
        sWd[d * 64 + nl] = wih0[j * (kDdyn + kEmb) + d];
    }
    __syncthreads();
    gridbar(bt);   // all bases read before any counter increments

    const int w = tid >> 5, lane = tid & 31;
    const int wm = w & 3, wn = w >> 2;
    const int g = lane >> 2, t4 = lane & 3;
    float* pp0 = g_part + (size_t)cta * (kB * 64);
    float* pp1 = g_part + (size_t)(kNCTA + cta) * (kB * 64);

    #pragma unroll 1
    for (int step = 0; step < kT; step++) {
        const int par = step & 1;
        // ===== layer 0 =====
        {
            if (step > 0) spinw(&g_d0, d0b + 32u * (unsigned)step);
            float acc[2][4][4];
            #pragma unroll
            for (int a = 0; a < 2; a++)
                #pragma unroll
                for (int b = 0; b < 4; b++)
                    #pragma unroll
                    for (int c = 0; c < 4; c++) acc[a][b][c] = 0.f;
            gemm_phase<2, 68>(g_h0h + par * (kB * kAW0), g_h0l + par * (kB * kAW0),
                              kAW0, kz * 64, sW0h, sW0l, Ah, Al, tid, wm, wn, g, t4, acc);
            #pragma unroll
            for (int mf = 0; mf < 2; mf++)
                #pragma unroll
                for (int nf = 0; nf < 4; nf++) {
                    int row = wm * 32 + mf * 16 + g, col = wn * 32 + nf * 8 + t4 * 2;
                    *(float2*)&pp0[row * 64 + col]       = make_float2(acc[mf][nf][0], acc[mf][nf][1]);
                    *(float2*)&pp0[(row + 8) * 64 + col] = make_float2(acc[mf][nf][2], acc[mf][nf][3]);
                }
            __threadfence();
            __syncthreads();
            if (tid == 0) sFlag = atomicAdd(&g_cnt0[ntile], 1u);
            __syncthreads();
            if ((sFlag & 3u) == 3u) {
                __threadfence();
                epilogue<0>(par, step, ntile, n0, tid, sWd, ctx, fut);
                __threadfence();
                __syncthreads();
                if (tid == 0) atomicAdd(&g_d0, 1u);
            }
        }
        // ===== layer 1 =====
        {
            if (kz < 2)       spinw(&g_d0, d0b + 32u * (unsigned)(step + 1));
            else if (step > 0) spinw(&g_d1, d1b + 32u * (unsigned)step);
            float acc[2][4][4];
            #pragma unroll
            for (int a = 0; a < 2; a++)
                #pragma unroll
                for (int b = 0; b < 4; b++)
                    #pragma unroll
                    for (int c = 0; c < 4; c++) acc[a][b][c] = 0.f;
            gemm_phase<4, 132>(g_i1h + par * (kB * kAW1), g_i1l + par * (kB * kAW1),
                               kAW1, kz * 128, sW1h, sW1l, Ah, Al, tid, wm, wn, g, t4, acc);
            #pragma unroll
            for (int mf = 0; mf < 2; mf++)
                #pragma unroll
                for (int nf = 0; nf < 4; nf++) {
                    int row = wm * 32 + mf * 16 + g, col = wn * 32 + nf * 8 + t4 * 2;
                    *(float2*)&pp1[row * 64 + col]       = make_float2(acc[mf][nf][0], acc[mf][nf][1]);
                    *(float2*)&pp1[(row + 8) * 64 + col] = make_float2(acc[mf][nf][2], acc[mf][nf][3]);
                }
            __threadfence();
            __syncthreads();
            if (tid == 0) sFlag = atomicAdd(&g_cnt1[ntile], 1u);
            __syncthreads();
            if ((sFlag & 3u) == 3u) {
                __threadfence();
                epilogue<1>(par, step, ntile, n0, tid, sWd, ctx, fut);
                __threadfence();
                __syncthreads();
                if (tid == 0) atomicAdd(&g_d1, 1u);
            }
        }
    }
}

// ---------------- head GEMMs ----------------
__global__ void __launch_bounds__(128) head1_gemm(const float* __restrict__ w1,
                                                  const float* __restrict__ b1) {
    __shared__ __align__(16) float As[2][16 * 68];
    __shared__ __align__(16) float Bs[2][16 * 36];
    const int tid = threadIdx.x;
    const int m0 = blockIdx.x * 64, n0 = blockIdx.y * 32;
    const int tm = tid & 15, tn = tid >> 4;
    constexpr int NT = kH / 16;
    float acc[4][4];
    #pragma unroll
    for (int i = 0; i < 4; i++)
        #pragma unroll
        for (int j = 0; j < 4; j++) acc[i][j] = 0.f;
    float ar[8]; float4 br;
    auto loadA = [&](int k0) {
        #pragma unroll
        for (int i = 0; i < 2; i++) {
            int li = tid * 2 + i, bb = li >> 2, kf = li & 3;
            float4 v = *reinterpret_cast<const float4*>(&g_Y1[(m0 + bb) * kH + k0 + kf * 4]);
            ar[i*4] = v.x; ar[i*4+1] = v.y; ar[i*4+2] = v.z; ar[i*4+3] = v.w;
        }
    };
    auto storeA = [&](int buf) {
        #pragma unroll
        for (int i = 0; i < 2; i++) {
            int li = tid * 2 + i, bb = li >> 2, kf = li & 3;
            #pragma unroll
            for (int j = 0; j < 4; j++) As[buf][(kf * 4 + j) * 68 + bb] = ar[i * 4 + j];
        }
    };
    auto loadB = [&](int k0) {
        int n = tid >> 2, kf = tid & 3;
        br = *reinterpret_cast<const float4*>(&w1[(n0 + n) * kH + k0 + kf * 4]);
    };
    auto storeB = [&](int buf) {
        int n = tid >> 2, kf = tid & 3;
        Bs[buf][(kf*4+0)*36+n] = br.x; Bs[buf][(kf*4+1)*36+n] = br.y;
        Bs[buf][(kf*4+2)*36+n] = br.z; Bs[buf][(kf*4+3)*36+n] = br.w;
    };
    loadA(0); loadB(0); storeA(0); storeB(0);
    __syncthreads();
    for (int kt = 0; kt < NT; ++kt) {
        int cur = kt & 1;
        if (kt + 1 < NT) { loadA((kt + 1) * 16); loadB((kt + 1) * 16); }
        #pragma unroll
        for (int kk = 0; kk < 16; ++kk) {
            float4 av = *reinterpret_cast<const float4*>(&As[cur][kk * 68 + tm * 4]);
            float4 bv = *reinterpret_cast<const float4*>(&Bs[cur][kk * 36 + tn * 4]);
            acc[0][0]+=av.x*bv.x; acc[0][1]+=av.x*bv.y; acc[0][2]+=av.x*bv.z; acc[0][3]+=av.x*bv.w;
            acc[1][0]+=av.y*bv.x; acc[1][1]+=av.y*bv.y; acc[1][2]+=av.y*bv.z; acc[1][3]+=av.y*bv.w;
            acc[2][0]+=av.z*bv.x; acc[2][1]+=av.z*bv.y; acc[2][2]+=av.z*bv.z; acc[2][3]+=av.z*bv.w;
            acc[3][0]+=av.w*bv.x; acc[3][1]+=av.w*bv.y; acc[3][2]+=av.w*bv.z; acc[3][3]+=av.w*bv.w;
        }
        if (kt + 1 < NT) { storeA(cur ^ 1); storeB(cur ^ 1); }
        __syncthreads();
    }
    #pragma unroll
    for (int i = 0; i < 4; i++) {
        int mg = m0 + tm * 4 + i;
        #pragma unroll
        for (int j = 0; j < 4; j++) {
            int ng = n0 + tn * 4 + j;
            g_hid[mg * kHid + ng] = fmaxf(acc[i][j] + b1[ng], 0.f);
        }
    }
}

__global__ void head2_kernel(const float* __restrict__ w2, const float* __restrict__ b2,
                             float* __restrict__ out) {
    int idx = blockIdx.x * 256 + threadIdx.x;
    int m = idx >> 2, o = idx & 3;
    const float4* hp = reinterpret_cast<const float4*>(g_hid + m * kHid);
    const float4* wp = reinterpret_cast<const float4*>(w2 + o * kHid);
    float s = 0.f;
    #pragma unroll 8
    for (int k = 0; k < kHid / 4; k++) {
        float4 a = hp[k], b = wp[k];
        s += a.x * b.x + a.y * b.y + a.z * b.z + a.w * b.w;
    }
    s += b2[o];
    int bb = m & (kB - 1), t = m >> 7;
    out[bb * (kPred * kOut) + t * kOut + o] = s;
}

extern "C" void kernel_launch(void* const* d_in, const int* in_sizes, int n_in,
                              void* d_out, int out_size) {
    const float* ctx   = (const float*)d_in[0];
    const float* sx    = (const float*)d_in[1];
    const float* fut   = (const float*)d_in[2];
    const float* mlpw1 = (const float*)d_in[3];
    const float* mlpb1 = (const float*)d_in[4];
    const float* mlpw2 = (const float*)d_in[5];
    const float* mlpb2 = (const float*)d_in[6];
    const float* embw  = (const float*)d_in[7];
    const float* embb  = (const float*)d_in[8];
    const float* wih0  = (const float*)d_in[9];
    const float* whh0  = (const float*)d_in[10];
    const float* bih0  = (const float*)d_in[11];
    const float* bhh0  = (const float*)d_in[12];
    const float* wih1  = (const float*)d_in[13];
    const float* whh1  = (const float*)d_in[14];
    const float* bih1  = (const float*)d_in[15];
    const float* bhh1  = (const float*)d_in[16];
    const float* hw1   = (const float*)d_in[17];
    const float* hb1   = (const float*)d_in[18];
    const float* hw2   = (const float*)d_in[19];
    const float* hb2   = (const float*)d_in[20];
    float* out = (float*)d_out;

    prep_mlp1<<<kB, kMlp>>>(sx, mlpw1, mlpb1);
    prep_emb<<<kB, kEmb>>>(sx, embw, embb);
    prep_init<<<dim3(kB, 4), 256>>>(mlpw2, mlpb2);
    prep_pre0<<<dim3(kB, 8), 256>>>(wih0, bih0, bhh0);
    prep_pre1<<<8, 256>>>(bih1, bhh1);

    cudaFuncSetAttribute(lstm_persist, cudaFuncAttributeMaxDynamicSharedMemorySize, kSmemBytes);
    lstm_persist<<<kNCTA, 256, kSmemBytes>>>(ctx, fut, whh0, wih0, wih1, whh1);

    head1_gemm<<<dim3(kM2 / 64, kHid / 32), 128>>>(hw1, hb1);
    head2_kernel<<<kM2 * kOut / 256, 256>>>(hw2, hb2, out);
}

// round 15
// speedup vs baseline: 1.1957x; 1.1957x over previous
#include <cuda_runtime.h>
#include <cuda_bf16.h>
#include <math.h>
#include <stdint.h>

constexpr int kB = 128, kH = 512, kCtx = 365, kPred = 90, kT = 455;
constexpr int kDdyn = 10, kEmb = 64, kStat = 36, kMlp = 128, kOut = 4;
constexpr int kNG = 2048, kNCTA = 128, kNTls = 32;
constexpr int kHid = 256, kM2 = kPred * kB;

// SMEM word offsets
constexpr int oW0h = 0;                 // 64 x 68
constexpr int oW0l = 4352;
constexpr int oW1h = 8704;              // 64 x 132
constexpr int oW1l = 17152;
constexpr int oWd  = 25600;             // f32 [10][64]
constexpr int oRing = 26240;            // 2 slots x (hi 128x36 + lo 128x36)
constexpr int kSmemBytes = (oRing + 2 * 9216) * 4;   // 178688

// global activation layout: [buf][kz][sub][arr(hi/lo)][128][36] words
// L0 (h0): 2 subs/kz (K slice = 128 elems = 64 words); L1 (y0|h1): 4 subs/kz
constexpr int kSlice = 9216;            // words per (kz,sub) block incl. both arrays
constexpr int kA0Buf = 4 * 2 * kSlice;  // 73728
constexpr int kA1Buf = 4 * 4 * kSlice;  // 147456
constexpr uint32_t kBulkBytes = kSlice * 4;   // 36864

__device__ float g_pre0[kB * kNG];
__device__ float g_pre1[kNG];
__device__ __align__(16) uint32_t g_a0[2 * kA0Buf];
__device__ __align__(16) uint32_t g_a1[2 * kA1Buf];
__device__ float g_c0[kB * kH];
__device__ float g_c1[kB * kH];
__device__ float g_emb[kB * kEmb];
__device__ float g_mlp1[kB * kMlp];
__device__ __align__(16) float g_part[kNCTA * kB * 64];
__device__ unsigned g_cnt[kNTls];
__device__ unsigned g_gen, g_barcnt;
__device__ __align__(16) float g_Y1[kM2 * kH];
__device__ __align__(16) float g_hid[kM2 * kHid];

__device__ __forceinline__ float sigm(float x) { return 1.f / (1.f + expf(-x)); }

__device__ __forceinline__ void split2(float e0, float e1, uint32_t& hi, uint32_t& lo) {
    float h0 = __bfloat162float(__float2bfloat16(e0));
    float h1 = __bfloat162float(__float2bfloat16(e1));
    asm("cvt.rn.bf16x2.f32 %0, %1, %2;" : "=r"(hi) : "f"(h1), "f"(h0));
    asm("cvt.rn.bf16x2.f32 %0, %1, %2;" : "=r"(lo) : "f"(e1 - h1), "f"(e0 - h0));
}

__device__ __forceinline__ void mma16(float c[4], const uint32_t a[4], uint32_t b0, uint32_t b1) {
    asm volatile("mma.sync.aligned.m16n8k16.row.col.f32.bf16.bf16.f32 "
                 "{%0,%1,%2,%3},{%4,%5,%6,%7},{%8,%9},{%0,%1,%2,%3};\n"
                 : "+f"(c[0]), "+f"(c[1]), "+f"(c[2]), "+f"(c[3])
                 : "r"(a[0]), "r"(a[1]), "r"(a[2]), "r"(a[3]), "r"(b0), "r"(b1));
}

__device__ __forceinline__ uint32_t s2u(const void* p) {
    return (uint32_t)__cvta_generic_to_shared(p);
}

// one bulk load: 36864B (hi+lo halves of one (kz,sub) slice) into a ring slot
__device__ __forceinline__ void bulk_ld(uint32_t sdst, const void* gsrc, uint32_t mbar) {
    asm volatile("mbarrier.arrive.expect_tx.shared.b64 _, [%0], %1;"
                 :: "r"(mbar), "r"(kBulkBytes) : "memory");
    asm volatile("cp.async.bulk.shared::cta.global.mbarrier::complete_tx::bytes "
                 "[%0], [%1], %2, [%3];"
                 :: "r"(sdst), "l"(gsrc), "r"(kBulkBytes), "r"(mbar) : "memory");
}

__device__ __forceinline__ void mbar_wait(uint32_t mbar, uint32_t parity) {
    uint32_t done;
    asm volatile(
        "{\n\t.reg .pred p;\n\t"
        "mbarrier.try_wait.parity.acquire.cta.shared::cta.b64 p, [%1], %2;\n\t"
        "selp.b32 %0, 1, 0, p;\n\t}"
        : "=r"(done) : "r"(mbar), "r"(parity) : "memory");
    if (!done) {
        asm volatile(
            "{\n\t.reg .pred P1;\n\t"
            "WL_%=:\n\t"
            "mbarrier.try_wait.parity.acquire.cta.shared::cta.b64 P1, [%0], %1, 0x989680;\n\t"
            "@P1 bra.uni WD_%=;\n\t"
            "bra.uni WL_%=;\n\t"
            "WD_%=:\n\t}"
            :: "r"(mbar), "r"(parity) : "memory");
    }
}

__device__ __forceinline__ void gridbar(unsigned& bt) {
    __threadfence();
    __syncthreads();
    if (threadIdx.x == 0) {
        unsigned arr = atomicAdd(&g_barcnt, 1u);
        if ((arr & (kNCTA - 1)) == kNCTA - 1) {
            asm volatile("st.release.gpu.global.u32 [%0], %1;" :: "l"(&g_gen), "r"(bt));
        } else {
            unsigned v;
            do { asm volatile("ld.acquire.gpu.global.u32 %0, [%1];" : "=r"(v) : "l"(&g_gen)); }
            while ((int)(v - bt) < 0);
        }
    }
    __syncthreads();
    bt++;
}

// ---------------- prep (5 launches) ----------------
__global__ void prep_mlp1(const float* __restrict__ sx, const float* __restrict__ w1,
                          const float* __restrict__ b1) {
    int b = blockIdx.x, m = threadIdx.x;
    float s = b1[m];
    #pragma unroll
    for (int d = 0; d < kStat; d++) s += sx[b * kStat + d] * w1[m * kStat + d];
    g_mlp1[b * kMlp + m] = fmaxf(s, 0.f);
}
__global__ void prep_emb(const float* __restrict__ sx, const float* __restrict__ ew,
                         const float* __restrict__ eb) {
    int b = blockIdx.x, e = threadIdx.x;
    float s = eb[e];
    #pragma unroll
    for (int d = 0; d < kStat; d++) s += sx[b * kStat + d] * ew[e * kStat + d];
    g_emb[b * kEmb + e] = fmaxf(s, 0.f);
}
__global__ void prep_init(const float* __restrict__ w2, const float* __restrict__ b2) {
    int b = blockIdx.x;
    int r = 2 * (blockIdx.y * 256 + threadIdx.x);
    float s0 = b2[r], s1 = b2[r + 1];
    #pragma unroll 4
    for (int m = 0; m < kMlp; m++) {
        float a = g_mlp1[b * kMlp + m];
        s0 += a * w2[r * kMlp + m];
        s1 += a * w2[(r + 1) * kMlp + m];
    }
    int ss = r >> 10, l = (r >> 9) & 1, h = r & 511;   // h even
    if (ss == 0) {
        uint32_t hi, lo; split2(s0, s1, hi, lo);
        if (l == 0) {                                   // h0 buf0, blocked layout
            int w = h >> 1;
            int o = ((w >> 6) * 2 + ((w >> 5) & 1)) * kSlice + b * 36 + (w & 31);
            g_a0[o] = hi; g_a0[o + 4608] = lo;
        } else {                                        // h1 buf0 (L1 word 256+w)
            int w = 256 + (h >> 1);
            int o = ((w >> 7) * 4 + ((w >> 5) & 3)) * kSlice + b * 36 + (w & 31);
            g_a1[o] = hi; g_a1[o + 4608] = lo;
        }
    } else {
        if (l == 0) { g_c0[b * kH + h] = s0; g_c0[b * kH + h + 1] = s1; }
        else        { g_c1[b * kH + h] = s0; g_c1[b * kH + h + 1] = s1; }
    }
}
__global__ void prep_pre0(const float* __restrict__ wih0, const float* __restrict__ bih,
                          const float* __restrict__ bhh) {
    int b = blockIdx.x;
    int n = blockIdx.y * 256 + threadIdx.x;
    int j = (n & 3) * kH + (n >> 2);
    float s = bih[j] + bhh[j];
    #pragma unroll 8
    for (int e = 0; e < kEmb; e++)
        s += g_emb[b * kEmb + e] * wih0[j * (kDdyn + kEmb) + kDdyn + e];
    g_pre0[b * kNG + n] = s;
}
__global__ void prep_pre1(const float* __restrict__ bih, const float* __restrict__ bhh) {
    int n = blockIdx.x * 256 + threadIdx.x;
    int j = (n & 3) * kH + (n >> 2);
    g_pre1[n] = bih[j] + bhh[j];
}

// ---------------- one K=64 sub-slice of MMA work (A already in SMEM) ----------------
template <int BSTR>
__device__ __forceinline__ void compute_sub(
    const uint32_t* __restrict__ Ah, const uint32_t* __restrict__ Al,
    const uint32_t* __restrict__ Bh, const uint32_t* __restrict__ Bl,
    int kbB, int wm, int wn, int g, int t4, float acc[2][4][4])
{
    #pragma unroll
    for (int s = 0; s < 4; s++) {
        int cw = s * 8;
        uint32_t ah[2][4], al[2][4];
        #pragma unroll
        for (int mf = 0; mf < 2; mf++) {
            int r0 = (wm * 32 + mf * 16 + g) * 36 + cw;
            int r1 = r0 + 8 * 36;
            ah[mf][0] = Ah[r0 + t4];     ah[mf][1] = Ah[r1 + t4];
            ah[mf][2] = Ah[r0 + 4 + t4]; ah[mf][3] = Ah[r1 + 4 + t4];
            al[mf][0] = Al[r0 + t4];     al[mf][1] = Al[r1 + t4];
            al[mf][2] = Al[r0 + 4 + t4]; al[mf][3] = Al[r1 + 4 + t4];
        }
        #pragma unroll
        for (int nf = 0; nf < 4; nf++) {
            int base = (wn * 32 + nf * 8 + g) * BSTR + kbB + cw;
            uint32_t bh0 = Bh[base + t4], bh1 = Bh[base + 4 + t4];
            uint32_t bl0 = Bl[base + t4], bl1 = Bl[base + 4 + t4];
            #pragma unroll
            for (int mf = 0; mf < 2; mf++) {
                mma16(acc[mf][nf], ah[mf], bh0, bh1);
                mma16(acc[mf][nf], ah[mf], bl0, bl1);
                mma16(acc[mf][nf], al[mf], bh0, bh1);
            }
        }
    }
}

// ---------------- K-split reduce + fused LSTM epilogue ----------------
template <int L>
__device__ __forceinline__ void epilogue(int par, int step, int ntile, int n0, int tid,
                                         const float* sWd,
                                         const float* __restrict__ ctx,
                                         const float* __restrict__ fut) {
    int m = tid >> 1, nh = (tid & 1) * 32;
    float s[32];
    #pragma unroll
    for (int j = 0; j < 32; j++) s[j] = 0.f;
    #pragma unroll 1
    for (int z = 0; z < 4; z++) {                      // fixed order -> deterministic
        const float4* q = reinterpret_cast<const float4*>(
            g_part + (size_t)(ntile * 4 + z) * (kB * 64) + m * 64 + nh);
        #pragma unroll
        for (int j = 0; j < 8; j++) {
            float4 v = __ldcg(q + j);
            s[j*4] += v.x; s[j*4+1] += v.y; s[j*4+2] += v.z; s[j*4+3] += v.w;
        }
    }
    if (L == 0) {                                      // dynamic-x term
        const float* xp = (step < kCtx)
            ? ctx + (size_t)m * (kCtx * kDdyn) + step * kDdyn
            : fut + (size_t)m * (kPred * kDdyn) + (step - kCtx) * kDdyn;
        #pragma unroll
        for (int d = 0; d < kDdyn; d++) {
            float xv = __ldg(xp + d);
            const float4* w4 = (const float4*)(sWd + d * 64 + nh);
            #pragma unroll
            for (int q = 0; q < 8; q++) {
                float4 w = w4[q];
                s[q*4]   += xv * w.x; s[q*4+1] += xv * w.y;
                s[q*4+2] += xv * w.z; s[q*4+3] += xv * w.w;
            }
        }
    }
    const float* pre = (L == 0) ? &g_pre0[m * kNG + n0 + nh] : &g_pre1[n0 + nh];
    float* cst = (L == 0) ? g_c0 : g_c1;
    float hv[8];
    #pragma unroll
    for (int j = 0; j < 32; j += 4) {
        int u = (n0 + nh + j) >> 2;
        float gi = s[j] + pre[j], gf = s[j+1] + pre[j+1];
        float gg = s[j+2] + pre[j+2], go = s[j+3] + pre[j+3];
        float iv = sigm(gi), fv = sigm(gf), gv = tanhf(gg), ov = sigm(go);
        float c = fv * __ldcg(&cst[m * kH + u]) + iv * gv;
        cst[m * kH + u] = c;
        hv[j >> 2] = ov * tanhf(c);
    }
    int wb = (n0 + nh) >> 3;                           // 4 words of packed h pairs
    if (L == 0) {
        uint32_t* a0 = g_a0 + (size_t)(par ^ 1) * kA0Buf;   // next-step h0
        uint32_t* a1 = g_a1 + (size_t)par * kA1Buf;         // y0 for this step's L1
        #pragma unroll
        for (int p = 0; p < 4; p++) {
            int w = wb + p;
            uint32_t hi, lo; split2(hv[2*p], hv[2*p+1], hi, lo);
            int o0 = ((w >> 6) * 2 + ((w >> 5) & 1)) * kSlice + m * 36 + (w & 31);
            a0[o0] = hi; a0[o0 + 4608] = lo;
            int o1 = ((w >> 7) * 4 + ((w >> 5) & 3)) * kSlice + m * 36 + (w & 31);
            a1[o1] = hi; a1[o1 + 4608] = lo;
        }
    } else {
        uint32_t* a1 = g_a1 + (size_t)(par ^ 1) * kA1Buf;   // next-step h1
        #pragma unroll
        for (int p = 0; p < 4; p++) {
            int w = 256 + wb + p;
            uint32_t hi, lo; split2(hv[2*p], hv[2*p+1], hi, lo);
            int o = ((w >> 7) * 4 + ((w >> 5) & 3)) * kSlice + m * 36 + (w & 31);
            a1[o] = hi; a1[o + 4608] = lo;
        }
        int trow = step - kCtx;
        if (trow >= 0) {
            int u0 = (n0 + nh) >> 2;
            #pragma unroll
            for (int p = 0; p < 8; p++)
                g_Y1[(size_t)(trow * kB + m) * kH + u0 + p] = hv[p];
        }
    }
}

// ---------------- persistent kernel ----------------
__global__ void __launch_bounds__(256, 1) lstm_persist(
    const float* __restrict__ ctx, const float* __restrict__ fut,
    const float* __restrict__ whh0, const float* __restrict__ wih0,
    const float* __restrict__ wih1, const float* __restrict__ whh1)
{
    extern __shared__ __align__(16) uint32_t smu[];
    uint32_t* sW0h = smu + oW0h; uint32_t* sW0l = smu + oW0l;
    uint32_t* sW1h = smu + oW1h; uint32_t* sW1l = smu + oW1l;
    float* sWd = (float*)(smu + oWd);
    uint32_t* rsH[2] = { smu + oRing, smu + oRing + 9216 };
    uint32_t* rsL[2] = { smu + oRing + 4608, smu + oRing + 13824 };
    __shared__ __align__(8) unsigned long long sMbar[2];
    __shared__ unsigned sFlag;

    const int tid = threadIdx.x, cta = blockIdx.x;
    const int ntile = cta >> 2, kz = cta & 3, n0 = ntile * 64;

    unsigned bt = *((volatile unsigned*)&g_gen) + 1;

    // weight slices -> SMEM (bf16 hi/lo pairs, interleaved gate rows)
    for (int idx = tid; idx < 64 * 64; idx += 256) {            // W0: 64n x 64 words
        int nl = idx >> 6, kw = idx & 63;
        int n = n0 + nl, j = (n & 3) * kH + (n >> 2);
        int k0 = kz * 128 + 2 * kw;
        uint32_t hi, lo;
        split2(whh0[j * kH + k0], whh0[j * kH + k0 + 1], hi, lo);
        sW0h[nl * 68 + kw] = hi; sW0l[nl * 68 + kw] = lo;
    }
    for (int idx = tid; idx < 64 * 128; idx += 256) {           // W1: 64n x 128 words
        int nl = idx >> 7, kw = idx & 127;
        int n = n0 + nl, j = (n & 3) * kH + (n >> 2);
        int k0 = kz * 256 + 2 * kw, k1 = k0 + 1;
        float v0 = (k0 < kH) ? wih1[j * kH + k0] : whh1[j * kH + k0 - kH];
        float v1 = (k1 < kH) ? wih1[j * kH + k1] : whh1[j * kH + k1 - kH];
        uint32_t hi, lo; split2(v0, v1, hi, lo);
        sW1h[nl * 132 + kw] = hi; sW1l[nl * 132 + kw] = lo;
    }
    for (int idx = tid; idx < kDdyn * 64; idx += 256) {         // Wd f32 [10][64]
        int d = idx >> 6, nl = idx & 63;
        int n = n0 + nl, j = (n & 3) * kH + (n >> 2);
        sWd[d * 64 + nl] = wih0[j * (kDdyn + kEmb) + d];
    }
    if (tid == 0) {
        asm volatile("mbarrier.init.shared.b64 [%0], 1;" :: "r"(s2u(&sMbar[0])) : "memory");
        asm volatile("mbarrier.init.shared.b64 [%0], 1;" :: "r"(s2u(&sMbar[1])) : "memory");
    }
    __syncthreads();
    gridbar(bt);

    const uint32_t mb0 = s2u(&sMbar[0]), mb1 = s2u(&sMbar[1]);
    const uint32_t rd0 = s2u(rsH[0]), rd1 = s2u(rsH[1]);
    const int w = tid >> 5, lane = tid & 31;
    const int wm = w & 3, wn = w >> 2;
    const int g = lane >> 2, t4 = lane & 3;
    float* pp = g_part + (size_t)cta * (kB * 64);
    unsigned p0 = 0, p1 = 0;

    #pragma unroll 1
    for (int step = 0; step < kT; step++) {
        const int par = step & 1;
        // ===== layer 0 (K-slice = 128 elems = 2 subs) =====
        {
            const uint32_t* src = g_a0 + (size_t)par * kA0Buf + (kz * 2) * kSlice;
            if (tid == 0) {
                bulk_ld(rd0, src, mb0);
                bulk_ld(rd1, src + kSlice, mb1);
            }
            float acc[2][4][4];
            #pragma unroll
            for (int a = 0; a < 2; a++)
                #pragma unroll
                for (int b = 0; b < 4; b++)
                    #pragma unroll
                    for (int c = 0; c < 4; c++) acc[a][b][c] = 0.f;
            mbar_wait(mb0, p0); p0 ^= 1;
            compute_sub<68>(rsH[0], rsL[0], sW0h, sW0l, 0, wm, wn, g, t4, acc);
            mbar_wait(mb1, p1); p1 ^= 1;
            compute_sub<68>(rsH[1], rsL[1], sW0h, sW0l, 32, wm, wn, g, t4, acc);
            #pragma unroll
            for (int mf = 0; mf < 2; mf++)
                #pragma unroll
                for (int nf = 0; nf < 4; nf++) {
                    int row = wm * 32 + mf * 16 + g, col = wn * 32 + nf * 8 + t4 * 2;
                    *(float2*)&pp[row * 64 + col]       = make_float2(acc[mf][nf][0], acc[mf][nf][1]);
                    *(float2*)&pp[(row + 8) * 64 + col] = make_float2(acc[mf][nf][2], acc[mf][nf][3]);
                }
            __threadfence();
            __syncthreads();
            if (tid == 0) sFlag = atomicAdd(&g_cnt[ntile], 1u);
            __syncthreads();
            if (sFlag == 3u) {
                if (tid == 0) g_cnt[ntile] = 0u;
                epilogue<0>(par, step, ntile, n0, tid, sWd, ctx, fut);
            }
            gridbar(bt);
        }
        // ===== layer 1 (K-slice = 256 elems = 4 subs) =====
        {
            const uint32_t* src = g_a1 + (size_t)par * kA1Buf + (kz * 4) * kSlice;
            if (tid == 0) {
                bulk_ld(rd0, src, mb0);
                bulk_ld(rd1, src + kSlice, mb1);
            }
            float acc[2][4][4];
            #pragma unroll
            for (int a = 0; a < 2; a++)
                #pragma unroll
                for (int b = 0; b < 4; b++)
                    #pragma unroll
                    for (int c = 0; c < 4; c++) acc[a][b][c] = 0.f;
            mbar_wait(mb0, p0); p0 ^= 1;
            compute_sub<132>(rsH[0], rsL[0], sW1h, sW1l, 0, wm, wn, g, t4, acc);
            __syncthreads();
            if (tid == 0) bulk_ld(rd0, src + 2 * kSlice, mb0);
            mbar_wait(mb1, p1); p1 ^= 1;
            compute_sub<132>(rsH[1], rsL[1], sW1h, sW1l, 32, wm, wn, g, t4, acc);
            __syncthreads();
            if (tid == 0) bulk_ld(rd1, src + 3 * kSlice, mb1);
            mbar_wait(mb0, p0); p0 ^= 1;
            compute_sub<132>(rsH[0], rsL[0], sW1h, sW1l, 64, wm, wn, g, t4, acc);
            mbar_wait(mb1, p1); p1 ^= 1;
            compute_sub<132>(rsH[1], rsL[1], sW1h, sW1l, 96, wm, wn, g, t4, acc);
            #pragma unroll
            for (int mf = 0; mf < 2; mf++)
                #pragma unroll
                for (int nf = 0; nf < 4; nf++) {
                    int row = wm * 32 + mf * 16 + g, col = wn * 32 + nf * 8 + t4 * 2;
                    *(float2*)&pp[row * 64 + col]       = make_float2(acc[mf][nf][0], acc[mf][nf][1]);
                    *(float2*)&pp[(row + 8) * 64 + col] = make_float2(acc[mf][nf][2], acc[mf][nf][3]);
                }
            __threadfence();
            __syncthreads();
            if (tid == 0) sFlag = atomicAdd(&g_cnt[ntile], 1u);
            __syncthreads();
            if (sFlag == 3u) {
                if (tid == 0) g_cnt[ntile] = 0u;
                epilogue<1>(par, step, ntile, n0, tid, sWd, ctx, fut);
            }
            gridbar(bt);
        }
    }
}

// ---------------- head GEMMs ----------------
__global__ void __launch_bounds__(128) head1_gemm(const float* __restrict__ w1,
                                                  const float* __restrict__ b1) {
    __shared__ __align__(16) float As[2][16 * 68];
    __shared__ __align__(16) float Bs[2][16 * 36];
    const int tid = threadIdx.x;
    const int m0 = blockIdx.x * 64, n0 = blockIdx.y * 32;
    const int tm = tid & 15, tn = tid >> 4;
    constexpr int NT = kH / 16;
    float acc[4][4];
    #pragma unroll
    for (int i = 0; i < 4; i++)
        #pragma unroll
        for (int j = 0; j < 4; j++) acc[i][j] = 0.f;
    float ar[8]; float4 br;
    auto loadA = [&](int k0) {
        #pragma unroll
        for (int i = 0; i < 2; i++) {
            int li = tid * 2 + i, bb = li >> 2, kf = li & 3;
            float4 v = *reinterpret_cast<const float4*>(&g_Y1[(m0 + bb) * kH + k0 + kf * 4]);
            ar[i*4] = v.x; ar[i*4+1] = v.y; ar[i*4+2] = v.z; ar[i*4+3] = v.w;
        }
    };
    auto storeA = [&](int buf) {
        #pragma unroll
        for (int i = 0; i < 2; i++) {
            int li = tid * 2 + i, bb = li >> 2, kf = li & 3;
            #pragma unroll
            for (int j = 0; j < 4; j++) As[buf][(kf * 4 + j) * 68 + bb] = ar[i * 4 + j];
        }
    };
    auto loadB = [&](int k0) {
        int n = tid >> 2, kf = tid & 3;
        br = *reinterpret_cast<const float4*>(&w1[(n0 + n) * kH + k0 + kf * 4]);
    };
    auto storeB = [&](int buf) {
        int n = tid >> 2, kf = tid & 3;
        Bs[buf][(kf*4+0)*36+n] = br.x; Bs[buf][(kf*4+1)*36+n] = br.y;
        Bs[buf][(kf*4+2)*36+n] = br.z; Bs[buf][(kf*4+3)*36+n] = br.w;
    };
    loadA(0); loadB(0); storeA(0); storeB(0);
    __syncthreads();
    for (int kt = 0; kt < NT; ++kt) {
        int cur = kt & 1;
        if (kt + 1 < NT) { loadA((kt + 1) * 16); loadB((kt + 1) * 16); }
        #pragma unroll
        for (int kk = 0; kk < 16; ++kk) {
            float4 av = *reinterpret_cast<const float4*>(&As[cur][kk * 68 + tm * 4]);
            float4 bv = *reinterpret_cast<const float4*>(&Bs[cur][kk * 36 + tn * 4]);
            acc[0][0]+=av.x*bv.x; acc[0][1]+=av.x*bv.y; acc[0][2]+=av.x*bv.z; acc[0][3]+=av.x*bv.w;
            acc[1][0]+=av.y*bv.x; acc[1][1]+=av.y*bv.y; acc[1][2]+=av.y*bv.z; acc[1][3]+=av.y*bv.w;
            acc[2][0]+=av.z*bv.x; acc[2][1]+=av.z*bv.y; acc[2][2]+=av.z*bv.z; acc[2][3]+=av.z*bv.w;
            acc[3][0]+=av.w*bv.x; acc[3][1]+=av.w*bv.y; acc[3][2]+=av.w*bv.z; acc[3][3]+=av.w*bv.w;
        }
        if (kt + 1 < NT) { storeA(cur ^ 1); storeB(cur ^ 1); }
        __syncthreads();
    }
    #pragma unroll
    for (int i = 0; i < 4; i++) {
        int mg = m0 + tm * 4 + i;
        #pragma unroll
        for (int j = 0; j < 4; j++) {
            int ng = n0 + tn * 4 + j;
            g_hid[mg * kHid + ng] = fmaxf(acc[i][j] + b1[ng], 0.f);
        }
    }
}

__global__ void head2_kernel(const float* __restrict__ w2, const float* __restrict__ b2,
                             float* __restrict__ out) {
    int idx = blockIdx.x * 256 + threadIdx.x;
    int m = idx >> 2, o = idx & 3;
    const float4* hp = reinterpret_cast<const float4*>(g_hid + m * kHid);
    const float4* wp = reinterpret_cast<const float4*>(w2 + o * kHid);
    float s = 0.f;
    #pragma unroll 8
    for (int k = 0; k < kHid / 4; k++) {
        float4 a = hp[k], b = wp[k];
        s += a.x * b.x + a.y * b.y + a.z * b.z + a.w * b.w;
    }
    s += b2[o];
    int bb = m & (kB - 1), t = m >> 7;
    out[bb * (kPred * kOut) + t * kOut + o] = s;
}

extern "C" void kernel_launch(void* const* d_in, const int* in_sizes, int n_in,
                              void* d_out, int out_size) {
    const float* ctx   = (const float*)d_in[0];
    const float* sx    = (const float*)d_in[1];
    const float* fut   = (const float*)d_in[2];
    const float* mlpw1 = (const float*)d_in[3];
    const float* mlpb1 = (const float*)d_in[4];
    const float* mlpw2 = (const float*)d_in[5];
    const float* mlpb2 = (const float*)d_in[6];
    const float* embw  = (const float*)d_in[7];
    const float* embb  = (const float*)d_in[8];
    const float* wih0  = (const float*)d_in[9];
    const float* whh0  = (const float*)d_in[10];
    const float* bih0  = (const float*)d_in[11];
    const float* bhh0  = (const float*)d_in[12];
    const float* wih1  = (const float*)d_in[13];
    const float* whh1  = (const float*)d_in[14];
    const float* bih1  = (const float*)d_in[15];
    const float* bhh1  = (const float*)d_in[16];
    const float* hw1   = (const float*)d_in[17];
    const float* hb1   = (const float*)d_in[18];
    const float* hw2   = (const float*)d_in[19];
    const float* hb2   = (const float*)d_in[20];
    float* out = (float*)d_out;

    prep_mlp1<<<kB, kMlp>>>(sx, mlpw1, mlpb1);
    prep_emb<<<kB, kEmb>>>(sx, embw, embb);
    prep_init<<<dim3(kB, 4), 256>>>(mlpw2, mlpb2);
    prep_pre0<<<dim3(kB, 8), 256>>>(wih0, bih0, bhh0);
    prep_pre1<<<8, 256>>>(bih1, bhh1);

    cudaFuncSetAttribute(lstm_persist, cudaFuncAttributeMaxDynamicSharedMemorySize, kSmemBytes);
    lstm_persist<<<kNCTA, 256, kSmemBytes>>>(ctx, fut, whh0, wih0, wih1, whh1);

    head1_gemm<<<dim3(kM2 / 64, kHid / 32), 128>>>(hw1, hb1);
    head2_kernel<<<kM2 * kOut / 256, 256>>>(hw2, hb2, out);
}

// round 16
// speedup vs baseline: 1.7213x; 1.4396x over previous
#include <cuda_runtime.h>
#include <cuda_bf16.h>
#include <math.h>
#include <stdint.h>

constexpr int kB = 128, kH = 512, kCtx = 365, kPred = 90, kT = 455;
constexpr int kDdyn = 10, kEmb = 64, kStat = 36, kMlp = 128, kOut = 4;
constexpr int kNG = 2048, kNCTA = 128, kNTls = 32;
constexpr int kHid = 256, kM2 = kPred * kB;

// SMEM word offsets
constexpr int oW0h = 0;                 // 64 x 68
constexpr int oW0l = 4352;
constexpr int oW1h = 8704;              // 64 x 132
constexpr int oW1l = 17152;
constexpr int oWd  = 25600;             // f32 [10][64]
constexpr int oRing = 26240;            // 2 slots x (hi 128x36 + lo 128x36)
constexpr int kSmemBytes = (oRing + 2 * 9216) * 4;   // 178688

// global activation layout: [buf][kz][sub][arr(hi/lo)][128][36] words
constexpr int kSlice = 9216;            // words per (kz,sub) block incl. hi+lo
constexpr int kA0Buf = 4 * 2 * kSlice;
constexpr int kA1Buf = 4 * 4 * kSlice;
constexpr uint32_t kBulkBytes = kSlice * 4;   // 36864

__device__ float g_pre0[kB * kNG];
__device__ float g_pre1[kNG];
__device__ __align__(16) uint32_t g_a0[2 * kA0Buf];
__device__ __align__(16) uint32_t g_a1[2 * kA1Buf];
__device__ float g_c0[kB * kH];
__device__ float g_c1[kB * kH];
__device__ float g_emb[kB * kEmb];
__device__ float g_mlp1[kB * kMlp];
__device__ __align__(16) float g_part[2 * kNCTA * kB * 64];   // per-layer planes
__device__ unsigned g_cnt0[kNTls], g_cnt1[kNTls];             // monotonic handoff
__device__ unsigned g_gen, g_barcnt;                          // 128-CTA barrier
__device__ unsigned g_gen64, g_bar64;                         // 64-CTA barrier (kz<2)
__device__ __align__(16) float g_Y1[kM2 * kH];
__device__ __align__(16) float g_hid[kM2 * kHid];

__device__ __forceinline__ float sigm(float x) { return 1.f / (1.f + expf(-x)); }

__device__ __forceinline__ void split2(float e0, float e1, uint32_t& hi, uint32_t& lo) {
    float h0 = __bfloat162float(__float2bfloat16(e0));
    float h1 = __bfloat162float(__float2bfloat16(e1));
    asm("cvt.rn.bf16x2.f32 %0, %1, %2;" : "=r"(hi) : "f"(h1), "f"(h0));
    asm("cvt.rn.bf16x2.f32 %0, %1, %2;" : "=r"(lo) : "f"(e1 - h1), "f"(e0 - h0));
}

__device__ __forceinline__ void mma16(float c[4], const uint32_t a[4], uint32_t b0, uint32_t b1) {
    asm volatile("mma.sync.aligned.m16n8k16.row.col.f32.bf16.bf16.f32 "
                 "{%0,%1,%2,%3},{%4,%5,%6,%7},{%8,%9},{%0,%1,%2,%3};\n"
                 : "+f"(c[0]), "+f"(c[1]), "+f"(c[2]), "+f"(c[3])
                 : "r"(a[0]), "r"(a[1]), "r"(a[2]), "r"(a[3]), "r"(b0), "r"(b1));
}

__device__ __forceinline__ uint32_t s2u(const void* p) {
    return (uint32_t)__cvta_generic_to_shared(p);
}

__device__ __forceinline__ void bulk_ld(uint32_t sdst, const void* gsrc, uint32_t mbar) {
    asm volatile("mbarrier.arrive.expect_tx.shared.b64 _, [%0], %1;"
                 :: "r"(mbar), "r"(kBulkBytes) : "memory");
    asm volatile("cp.async.bulk.shared::cta.global.mbarrier::complete_tx::bytes "
                 "[%0], [%1], %2, [%3];"
                 :: "r"(sdst), "l"(gsrc), "r"(kBulkBytes), "r"(mbar) : "memory");
}

__device__ __forceinline__ void mbar_wait(uint32_t mbar, uint32_t parity) {
    uint32_t done;
    asm volatile(
        "{\n\t.reg .pred p;\n\t"
        "mbarrier.try_wait.parity.acquire.cta.shared::cta.b64 p, [%1], %2;\n\t"
        "selp.b32 %0, 1, 0, p;\n\t}"
        : "=r"(done) : "r"(mbar), "r"(parity) : "memory");
    if (!done) {
        asm volatile(
            "{\n\t.reg .pred P1;\n\t"
            "WL_%=:\n\t"
            "mbarrier.try_wait.parity.acquire.cta.shared::cta.b64 P1, [%0], %1, 0x989680;\n\t"
            "@P1 bra.uni WD_%=;\n\t"
            "bra.uni WL_%=;\n\t"
            "WD_%=:\n\t}"
            :: "r"(mbar), "r"(parity) : "memory");
    }
}

// full-grid barrier (128 CTAs)
__device__ __forceinline__ void gridbar(unsigned& bt) {
    __threadfence();
    __syncthreads();
    if (threadIdx.x == 0) {
        unsigned arr = atomicAdd(&g_barcnt, 1u);
        if ((arr & (kNCTA - 1)) == kNCTA - 1) {
            asm volatile("st.release.gpu.global.u32 [%0], %1;" :: "l"(&g_gen), "r"(bt));
        } else {
            unsigned v;
            do { asm volatile("ld.acquire.gpu.global.u32 %0, [%1];" : "=r"(v) : "l"(&g_gen)); }
            while ((int)(v - bt) < 0);
        }
    }
    __syncthreads();
    bt++;
}

// 64-CTA barrier (only kz<2 CTAs participate)
__device__ __forceinline__ void gridbar64(unsigned& bt) {
    __threadfence();
    __syncthreads();
    if (threadIdx.x == 0) {
        unsigned arr = atomicAdd(&g_bar64, 1u);
        if ((arr & 63u) == 63u) {
            asm volatile("st.release.gpu.global.u32 [%0], %1;" :: "l"(&g_gen64), "r"(bt));
        } else {
            unsigned v;
            do { asm volatile("ld.acquire.gpu.global.u32 %0, [%1];" : "=r"(v) : "l"(&g_gen64)); }
            while ((int)(v - bt) < 0);
        }
    }
    __syncthreads();
    bt++;
}

__device__ __forceinline__ void spin_cnt(unsigned* p, unsigned tgt) {
    if (threadIdx.x == 0) {
        unsigned v;
        do { asm volatile("ld.acquire.gpu.global.u32 %0, [%1];" : "=r"(v) : "l"(p)); }
        while ((int)(v - tgt) < 0);
    }
    __syncthreads();
}

// ---------------- prep (EXACTLY 3 launches so lstm_persist = global launch #5) ----------------
__global__ void prepA(const float* __restrict__ sx, const float* __restrict__ w1,
                      const float* __restrict__ b1, const float* __restrict__ ew,
                      const float* __restrict__ eb) {
    int b = blockIdx.x, t = threadIdx.x;         // 192 threads
    if (t < kMlp) {
        float s = b1[t];
        #pragma unroll
        for (int d = 0; d < kStat; d++) s += sx[b * kStat + d] * w1[t * kStat + d];
        g_mlp1[b * kMlp + t] = fmaxf(s, 0.f);
    } else {
        int e = t - kMlp;
        float s = eb[e];
        #pragma unroll
        for (int d = 0; d < kStat; d++) s += sx[b * kStat + d] * ew[e * kStat + d];
        g_emb[b * kEmb + e] = fmaxf(s, 0.f);
    }
}

__global__ void prepB(const float* __restrict__ w2, const float* __restrict__ b2) {
    int b = blockIdx.x;
    int r = 2 * (blockIdx.y * 256 + threadIdx.x);
    float s0 = b2[r], s1 = b2[r + 1];
    #pragma unroll 4
    for (int m = 0; m < kMlp; m++) {
        float a = g_mlp1[b * kMlp + m];
        s0 += a * w2[r * kMlp + m];
        s1 += a * w2[(r + 1) * kMlp + m];
    }
    int ss = r >> 10, l = (r >> 9) & 1, h = r & 511;   // h even
    if (ss == 0) {
        uint32_t hi, lo; split2(s0, s1, hi, lo);
        if (l == 0) {
            int w = h >> 1;
            int o = ((w >> 6) * 2 + ((w >> 5) & 1)) * kSlice + b * 36 + (w & 31);
            g_a0[o] = hi; g_a0[o + 4608] = lo;
        } else {
            int w = 256 + (h >> 1);
            int o = ((w >> 7) * 4 + ((w >> 5) & 3)) * kSlice + b * 36 + (w & 31);
            g_a1[o] = hi; g_a1[o + 4608] = lo;
        }
    } else {
        if (l == 0) { g_c0[b * kH + h] = s0; g_c0[b * kH + h + 1] = s1; }
        else        { g_c1[b * kH + h] = s0; g_c1[b * kH + h + 1] = s1; }
    }
}

__global__ void prepC(const float* __restrict__ wih0, const float* __restrict__ bih0,
                      const float* __restrict__ bhh0, const float* __restrict__ bih1,
                      const float* __restrict__ bhh1) {
    int b = blockIdx.x;
    int n = blockIdx.y * 256 + threadIdx.x;
    int j = (n & 3) * kH + (n >> 2);
    float s = bih0[j] + bhh0[j];
    #pragma unroll 8
    for (int e = 0; e < kEmb; e++)
        s += g_emb[b * kEmb + e] * wih0[j * (kDdyn + kEmb) + kDdyn + e];
    g_pre0[b * kNG + n] = s;
    if (b == 0) g_pre1[n] = bih1[j] + bhh1[j];
}

// ---------------- one K=64 sub-slice of MMA work ----------------
template <int BSTR>
__device__ __forceinline__ void compute_sub(
    const uint32_t* __restrict__ Ah, const uint32_t* __restrict__ Al,
    const uint32_t* __restrict__ Bh, const uint32_t* __restrict__ Bl,
    int kbB, int wm, int wn, int g, int t4, float acc[2][4][4])
{
    #pragma unroll
    for (int s = 0; s < 4; s++) {
        int cw = s * 8;
        uint32_t ah[2][4], al[2][4];
        #pragma unroll
        for (int mf = 0; mf < 2; mf++) {
            int r0 = (wm * 32 + mf * 16 + g) * 36 + cw;
            int r1 = r0 + 8 * 36;
            ah[mf][0] = Ah[r0 + t4];     ah[mf][1] = Ah[r1 + t4];
            ah[mf][2] = Ah[r0 + 4 + t4]; ah[mf][3] = Ah[r1 + 4 + t4];
            al[mf][0] = Al[r0 + t4];     al[mf][1] = Al[r1 + t4];
            al[mf][2] = Al[r0 + 4 + t4]; al[mf][3] = Al[r1 + 4 + t4];
        }
        #pragma unroll
        for (int nf = 0; nf < 4; nf++) {
            int base = (wn * 32 + nf * 8 + g) * BSTR + kbB + cw;
            uint32_t bh0 = Bh[base + t4], bh1 = Bh[base + 4 + t4];
            uint32_t bl0 = Bl[base + t4], bl1 = Bl[base + 4 + t4];
            #pragma unroll
            for (int mf = 0; mf < 2; mf++) {
                mma16(acc[mf][nf], ah[mf], bh0, bh1);
                mma16(acc[mf][nf], ah[mf], bl0, bl1);
                mma16(acc[mf][nf], al[mf], bh0, bh1);
            }
        }
    }
}

// ---------------- half-epilogue: 128 rows x 32 cols (half 0/1 of one ntile) ----------------
template <int L>
__device__ __forceinline__ void epilogue_half(int par, int step, int ntile, int n0, int half,
                                              int tid, const float* sWd,
                                              const float* __restrict__ ctx,
                                              const float* __restrict__ fut) {
    int m = tid >> 1;
    int nh = half * 32 + (tid & 1) * 16;
    float s[16];
    #pragma unroll
    for (int j = 0; j < 16; j++) s[j] = 0.f;
    #pragma unroll 1
    for (int z = 0; z < 4; z++) {                      // fixed order -> deterministic
        const float4* q = reinterpret_cast<const float4*>(
            g_part + (size_t)(L * kNCTA + ntile * 4 + z) * (kB * 64) + m * 64 + nh);
        #pragma unroll
        for (int j = 0; j < 4; j++) {
            float4 v = __ldcg(q + j);
            s[j*4] += v.x; s[j*4+1] += v.y; s[j*4+2] += v.z; s[j*4+3] += v.w;
        }
    }
    if (L == 0) {                                      // dynamic-x term
        const float* xp = (step < kCtx)
            ? ctx + (size_t)m * (kCtx * kDdyn) + step * kDdyn
            : fut + (size_t)m * (kPred * kDdyn) + (step - kCtx) * kDdyn;
        #pragma unroll
        for (int d = 0; d < kDdyn; d++) {
            float xv = __ldg(xp + d);
            const float4* w4 = (const float4*)(sWd + d * 64 + nh);
            #pragma unroll
            for (int q = 0; q < 4; q++) {
                float4 w = w4[q];
                s[q*4]   += xv * w.x; s[q*4+1] += xv * w.y;
                s[q*4+2] += xv * w.z; s[q*4+3] += xv * w.w;
            }
        }
    }
    const float* pre = (L == 0) ? &g_pre0[m * kNG + n0 + nh] : &g_pre1[n0 + nh];
    float* cst = (L == 0) ? g_c0 : g_c1;
    float hv[4];
    #pragma unroll
    for (int j = 0; j < 16; j += 4) {
        int u = (n0 + nh + j) >> 2;
        float gi = s[j] + pre[j], gf = s[j+1] + pre[j+1];
        float gg = s[j+2] + pre[j+2], go = s[j+3] + pre[j+3];
        float iv = sigm(gi), fv = sigm(gf), gv = tanhf(gg), ov = sigm(go);
        float c = fv * __ldcg(&cst[m * kH + u]) + iv * gv;
        cst[m * kH + u] = c;
        hv[j >> 2] = ov * tanhf(c);
    }
    int wb = (n0 + nh) >> 3;                           // 2 packed words
    if (L == 0) {
        uint32_t* a0 = g_a0 + (size_t)(par ^ 1) * kA0Buf;   // next-step h0
        uint32_t* a1 = g_a1 + (size_t)par * kA1Buf;         // y0 for this step's L1
        #pragma unroll
        for (int p = 0; p < 2; p++) {
            int w = wb + p;
            uint32_t hi, lo; split2(hv[2*p], hv[2*p+1], hi, lo);
            int o0 = ((w >> 6) * 2 + ((w >> 5) & 1)) * kSlice + m * 36 + (w & 31);
            a0[o0] = hi; a0[o0 + 4608] = lo;
            int o1 = ((w >> 7) * 4 + ((w >> 5) & 3)) * kSlice + m * 36 + (w & 31);
            a1[o1] = hi; a1[o1 + 4608] = lo;
        }
    } else {
        uint32_t* a1 = g_a1 + (size_t)(par ^ 1) * kA1Buf;   // next-step h1
        #pragma unroll
        for (int p = 0; p < 2; p++) {
            int w = 256 + wb + p;
            uint32_t hi, lo; split2(hv[2*p], hv[2*p+1], hi, lo);
            int o = ((w >> 7) * 4 + ((w >> 5) & 3)) * kSlice + m * 36 + (w & 31);
            a1[o] = hi; a1[o + 4608] = lo;
        }
        int trow = step - kCtx;
        if (trow >= 0) {
            int u0 = (n0 + nh) >> 2;
            #pragma unroll
            for (int p = 0; p < 4; p++)
                g_Y1[(size_t)(trow * kB + m) * kH + u0 + p] = hv[p];
        }
    }
}

// ---------------- persistent kernel ----------------
__global__ void __launch_bounds__(256, 1) lstm_persist(
    const float* __restrict__ ctx, const float* __restrict__ fut,
    const float* __restrict__ whh0, const float* __restrict__ wih0,
    const float* __restrict__ wih1, const float* __restrict__ whh1)
{
    extern __shared__ __align__(16) uint32_t smu[];
    uint32_t* sW0h = smu + oW0h; uint32_t* sW0l = smu + oW0l;
    uint32_t* sW1h = smu + oW1h; uint32_t* sW1l = smu + oW1l;
    float* sWd = (float*)(smu + oWd);
    uint32_t* rsH[2] = { smu + oRing, smu + oRing + 9216 };
    uint32_t* rsL[2] = { smu + oRing + 4608, smu + oRing + 13824 };
    __shared__ __align__(8) unsigned long long sMbar[2];

    const int tid = threadIdx.x, cta = blockIdx.x;
    const int ntile = cta >> 2, kz = cta & 3, n0 = ntile * 64;

    unsigned bt   = *((volatile unsigned*)&g_gen) + 1;
    unsigned bt64 = *((volatile unsigned*)&g_gen64) + 1;
    unsigned c0b  = *((volatile unsigned*)&g_cnt0[ntile]);
    unsigned c1b  = *((volatile unsigned*)&g_cnt1[ntile]);

    // weight slices -> SMEM (bf16 hi/lo pairs, interleaved gate rows)
    for (int idx = tid; idx < 64 * 64; idx += 256) {
        int nl = idx >> 6, kw = idx & 63;
        int n = n0 + nl, j = (n & 3) * kH + (n >> 2);
        int k0 = kz * 128 + 2 * kw;
        uint32_t hi, lo;
        split2(whh0[j * kH + k0], whh0[j * kH + k0 + 1], hi, lo);
        sW0h[nl * 68 + kw] = hi; sW0l[nl * 68 + kw] = lo;
    }
    for (int idx = tid; idx < 64 * 128; idx += 256) {
        int nl = idx >> 7, kw = idx & 127;
        int n = n0 + nl, j = (n & 3) * kH + (n >> 2);
        int k0 = kz * 256 + 2 * kw, k1 = k0 + 1;
        float v0 = (k0 < kH) ? wih1[j * kH + k0] : whh1[j * kH + k0 - kH];
        float v1 = (k1 < kH) ? wih1[j * kH + k1] : whh1[j * kH + k1 - kH];
        uint32_t hi, lo; split2(v0, v1, hi, lo);
        sW1h[nl * 132 + kw] = hi; sW1l[nl * 132 + kw] = lo;
    }
    for (int idx = tid; idx < kDdyn * 64; idx += 256) {
        int d = idx >> 6, nl = idx & 63;
        int n = n0 + nl, j = (n & 3) * kH + (n >> 2);
        sWd[d * 64 + nl] = wih0[j * (kDdyn + kEmb) + d];
    }
    if (tid == 0) {
        asm volatile("mbarrier.init.shared.b64 [%0], 1;" :: "r"(s2u(&sMbar[0])) : "memory");
        asm volatile("mbarrier.init.shared.b64 [%0], 1;" :: "r"(s2u(&sMbar[1])) : "memory");
    }
    __syncthreads();
    gridbar(bt);   // all bases read + weights staged before any counter bumps

    const uint32_t mb0 = s2u(&sMbar[0]), mb1 = s2u(&sMbar[1]);
    const uint32_t rd0 = s2u(rsH[0]), rd1 = s2u(rsH[1]);
    const int w = tid >> 5, lane = tid & 31;
    const int wm = w & 3, wn = w >> 2;
    const int g = lane >> 2, t4 = lane & 3;
    float* pp0 = g_part + (size_t)cta * (kB * 64);
    float* pp1 = g_part + (size_t)(kNCTA + cta) * (kB * 64);
    unsigned p0 = 0, p1 = 0;

    #pragma unroll 1
    for (int step = 0; step < kT; step++) {
        const int par = step & 1;
        // ===== layer 0 GEMM (all CTAs) =====
        {
            const uint32_t* src = g_a0 + (size_t)par * kA0Buf + (kz * 2) * kSlice;
            if (tid == 0) { bulk_ld(rd0, src, mb0); bulk_ld(rd1, src + kSlice, mb1); }
            float acc[2][4][4];
            #pragma unroll
            for (int a = 0; a < 2; a++)
                #pragma unroll
                for (int b = 0; b < 4; b++)
                    #pragma unroll
                    for (int c = 0; c < 4; c++) acc[a][b][c] = 0.f;
            mbar_wait(mb0, p0); p0 ^= 1;
            compute_sub<68>(rsH[0], rsL[0], sW0h, sW0l, 0, wm, wn, g, t4, acc);
            mbar_wait(mb1, p1); p1 ^= 1;
            compute_sub<68>(rsH[1], rsL[1], sW0h, sW0l, 32, wm, wn, g, t4, acc);
            #pragma unroll
            for (int mf = 0; mf < 2; mf++)
                #pragma unroll
                for (int nf = 0; nf < 4; nf++) {
                    int row = wm * 32 + mf * 16 + g, col = wn * 32 + nf * 8 + t4 * 2;
                    *(float2*)&pp0[row * 64 + col]       = make_float2(acc[mf][nf][0], acc[mf][nf][1]);
                    *(float2*)&pp0[(row + 8) * 64 + col] = make_float2(acc[mf][nf][2], acc[mf][nf][3]);
                }
            __threadfence();
            __syncthreads();
            if (tid == 0) atomicAdd(&g_cnt0[ntile], 1u);
        }
        // ===== diverge: kz<2 do epi0 + bar64 then L1(y0); kz>=2 go straight to L1(h1) =====
        if (kz < 2) {
            spin_cnt(&g_cnt0[ntile], c0b + 4u * (unsigned)(step + 1));
            epilogue_half<0>(par, step, ntile, n0, kz, tid, sWd, ctx, fut);
            gridbar64(bt64);                       // all epi0 done chip-wide -> y0 readable
        }
        {
            const uint32_t* src = g_a1 + (size_t)par * kA1Buf + (kz * 4) * kSlice;
            if (tid == 0) { bulk_ld(rd0, src, mb0); bulk_ld(rd1, src + kSlice, mb1); }
            float acc[2][4][4];
            #pragma unroll
            for (int a = 0; a < 2; a++)
                #pragma unroll
                for (int b = 0; b < 4; b++)
                    #pragma unroll
                    for (int c = 0; c < 4; c++) acc[a][b][c] = 0.f;
            mbar_wait(mb0, p0); p0 ^= 1;
            compute_sub<132>(rsH[0], rsL[0], sW1h, sW1l, 0, wm, wn, g, t4, acc);
            __syncthreads();
            if (tid == 0) bulk_ld(rd0, src + 2 * kSlice, mb0);
            mbar_wait(mb1, p1); p1 ^= 1;
            compute_sub<132>(rsH[1], rsL[1], sW1h, sW1l, 32, wm, wn, g, t4, acc);
            __syncthreads();
            if (tid == 0) bulk_ld(rd1, src + 3 * kSlice, mb1);
            mbar_wait(mb0, p0); p0 ^= 1;
            compute_sub<132>(rsH[0], rsL[0], sW1h, sW1l, 64, wm, wn, g, t4, acc);
            mbar_wait(mb1, p1); p1 ^= 1;
            compute_sub<132>(rsH[1], rsL[1], sW1h, sW1l, 96, wm, wn, g, t4, acc);
            #pragma unroll
            for (int mf = 0; mf < 2; mf++)
                #pragma unroll
                for (int nf = 0; nf < 4; nf++) {
                    int row = wm * 32 + mf * 16 + g, col = wn * 32 + nf * 8 + t4 * 2;
                    *(float2*)&pp1[row * 64 + col]       = make_float2(acc[mf][nf][0], acc[mf][nf][1]);
                    *(float2*)&pp1[(row + 8) * 64 + col] = make_float2(acc[mf][nf][2], acc[mf][nf][3]);
                }
            __threadfence();
            __syncthreads();
            if (tid == 0) atomicAdd(&g_cnt1[ntile], 1u);
        }
        if (kz >= 2) {
            spin_cnt(&g_cnt1[ntile], c1b + 4u * (unsigned)(step + 1));
            epilogue_half<1>(par, step, ntile, n0, kz - 2, tid, sWd, ctx, fut);
        }
        gridbar(bt);                               // epi1 done chip-wide -> next step
    }
}

// ---------------- head GEMMs ----------------
__global__ void __launch_bounds__(128) head1_gemm(const float* __restrict__ w1,
                                                  const float* __restrict__ b1) {
    __shared__ __align__(16) float As[2][16 * 68];
    __shared__ __align__(16) float Bs[2][16 * 36];
    const int tid = threadIdx.x;
    const int m0 = blockIdx.x * 64, n0 = blockIdx.y * 32;
    const int tm = tid & 15, tn = tid >> 4;
    constexpr int NT = kH / 16;
    float acc[4][4];
    #pragma unroll
    for (int i = 0; i < 4; i++)
        #pragma unroll
        for (int j = 0; j < 4; j++) acc[i][j] = 0.f;
    float ar[8]; float4 br;
    auto loadA = [&](int k0) {
        #pragma unroll
        for (int i = 0; i < 2; i++) {
            int li = tid * 2 + i, bb = li >> 2, kf = li & 3;
            float4 v = *reinterpret_cast<const float4*>(&g_Y1[(m0 + bb) * kH + k0 + kf * 4]);
            ar[i*4] = v.x; ar[i*4+1] = v.y; ar[i*4+2] = v.z; ar[i*4+3] = v.w;
        }
    };
    auto storeA = [&](int buf) {
        #pragma unroll
        for (int i = 0; i < 2; i++) {
            int li = tid * 2 + i, bb = li >> 2, kf = li & 3;
            #pragma unroll
            for (int j = 0; j < 4; j++) As[buf][(kf * 4 + j) * 68 + bb] = ar[i * 4 + j];
        }
    };
    auto loadB = [&](int k0) {
        int n = tid >> 2, kf = tid & 3;
        br = *reinterpret_cast<const float4*>(&w1[(n0 + n) * kH + k0 + kf * 4]);
    };
    auto storeB = [&](int buf) {
        int n = tid >> 2, kf = tid & 3;
        Bs[buf][(kf*4+0)*36+n] = br.x; Bs[buf][(kf*4+1)*36+n] = br.y;
        Bs[buf][(kf*4+2)*36+n] = br.z; Bs[buf][(kf*4+3)*36+n] = br.w;
    };
    loadA(0); loadB(0); storeA(0); storeB(0);
    __syncthreads();
    for (int kt = 0; kt < NT; ++kt) {
        int cur = kt & 1;
        if (kt + 1 < NT) { loadA((kt + 1) * 16); loadB((kt + 1) * 16); }
        #pragma unroll
        for (int kk = 0; kk < 16; ++kk) {
            float4 av = *reinterpret_cast<const float4*>(&As[cur][kk * 68 + tm * 4]);
            float4 bv = *reinterpret_cast<const float4*>(&Bs[cur][kk * 36 + tn * 4]);
            acc[0][0]+=av.x*bv.x; acc[0][1]+=av.x*bv.y; acc[0][2]+=av.x*bv.z; acc[0][3]+=av.x*bv.w;
            acc[1][0]+=av.y*bv.x; acc[1][1]+=av.y*bv.y; acc[1][2]+=av.y*bv.z; acc[1][3]+=av.y*bv.w;
            acc[2][0]+=av.z*bv.x; acc[2][1]+=av.z*bv.y; acc[2][2]+=av.z*bv.z; acc[2][3]+=av.z*bv.w;
            acc[3][0]+=av.w*bv.x; acc[3][1]+=av.w*bv.y; acc[3][2]+=av.w*bv.z; acc[3][3]+=av.w*bv.w;
        }
        if (kt + 1 < NT) { storeA(cur ^ 1); storeB(cur ^ 1); }
        __syncthreads();
    }
    #pragma unroll
    for (int i = 0; i < 4; i++) {
        int mg = m0 + tm * 4 + i;
        #pragma unroll
        for (int j = 0; j < 4; j++) {
            int ng = n0 + tn * 4 + j;
            g_hid[mg * kHid + ng] = fmaxf(acc[i][j] + b1[ng], 0.f);
        }
    }
}

__global__ void head2_kernel(const float* __restrict__ w2, const float* __restrict__ b2,
                             float* __restrict__ out) {
    int idx = blockIdx.x * 256 + threadIdx.x;
    int m = idx >> 2, o = idx & 3;
    const float4* hp = reinterpret_cast<const float4*>(g_hid + m * kHid);
    const float4* wp = reinterpret_cast<const float4*>(w2 + o * kHid);
    float s = 0.f;
    #pragma unroll 8
    for (int k = 0; k < kHid / 4; k++) {
        float4 a = hp[k], b = wp[k];
        s += a.x * b.x + a.y * b.y + a.z * b.z + a.w * b.w;
    }
    s += b2[o];
    int bb = m & (kB - 1), t = m >> 7;
    out[bb * (kPred * kOut) + t * kOut + o] = s;
}

extern "C" void kernel_launch(void* const* d_in, const int* in_sizes, int n_in,
                              void* d_out, int out_size) {
    const float* ctx   = (const float*)d_in[0];
    const float* sx    = (const float*)d_in[1];
    const float* fut   = (const float*)d_in[2];
    const float* mlpw1 = (const float*)d_in[3];
    const float* mlpb1 = (const float*)d_in[4];
    const float* mlpw2 = (const float*)d_in[5];
    const float* mlpb2 = (const float*)d_in[6];
    const float* embw  = (const float*)d_in[7];
    const float* embb  = (const float*)d_in[8];
    const float* wih0  = (const float*)d_in[9];
    const float* whh0  = (const float*)d_in[10];
    const float* bih0  = (const float*)d_in[11];
    const float* bhh0  = (const float*)d_in[12];
    const float* wih1  = (const float*)d_in[13];
    const float* whh1  = (const float*)d_in[14];
    const float* bih1  = (const float*)d_in[15];
    const float* bhh1  = (const float*)d_in[16];
    const float* hw1   = (const float*)d_in[17];
    const float* hb1   = (const float*)d_in[18];
    const float* hw2   = (const float*)d_in[19];
    const float* hb2   = (const float*)d_in[20];
    float* out = (float*)d_out;

    // exactly 3 preps -> lstm_persist is global launch #5 (harness injects 2) -> ncu captures it
    prepA<<<kB, 192>>>(sx, mlpw1, mlpb1, embw, embb);
    prepB<<<dim3(kB, 4), 256>>>(mlpw2, mlpb2);
    prepC<<<dim3(kB, 8), 256>>>(wih0, bih0, bhh0, bih1, bhh1);

    cudaFuncSetAttribute(lstm_persist, cudaFuncAttributeMaxDynamicSharedMemorySize, kSmemBytes);
    lstm_persist<<<kNCTA, 256, kSmemBytes>>>(ctx, fut, whh0, wih0, wih1, whh1);

    head1_gemm<<<dim3(kM2 / 64, kHid / 32), 128>>>(hw1, hb1);
    head2_kernel<<<kM2 * kOut / 256, 256>>>(hw2, hb2, out);
}

// round 17
// speedup vs baseline: 1.8401x; 1.0690x over previous
#include <cuda_runtime.h>
#include <cuda_bf16.h>
#include <math.h>
#include <stdint.h>

constexpr int kB = 128, kH = 512, kCtx = 365, kPred = 90, kT = 455;
constexpr int kDdyn = 10, kEmb = 64, kStat = 36, kMlp = 128, kOut = 4;
constexpr int kNG = 2048, kNCTA = 128, kNTls = 32;
constexpr int kHid = 256, kM2 = kPred * kB;

// SMEM word offsets
constexpr int oW0h = 0;                 // 64 x 68
constexpr int oW0l = 4352;
constexpr int oW1h = 8704;              // 64 x 132
constexpr int oW1l = 17152;
constexpr int oWd  = 25600;             // f32 [10][64]
constexpr int oRing = 26240;            // 2 slots x (hi 128x36 + lo 128x36)
constexpr int kSmemBytes = (oRing + 2 * 9216) * 4;   // 178688

// global activation layout: [buf][kz][sub][arr(hi/lo)][128][36] words
constexpr int kSlice = 9216;
constexpr int kA0Buf = 4 * 2 * kSlice;
constexpr int kA1Buf = 4 * 4 * kSlice;
constexpr uint32_t kBulkBytes = kSlice * 4;   // 36864

__device__ float g_pre0[kB * kNG];
__device__ float g_pre1[kNG];
__device__ __align__(16) uint32_t g_a0[2 * kA0Buf];
__device__ __align__(16) uint32_t g_a1[2 * kA1Buf];
__device__ float g_c0[kB * kH];
__device__ float g_c1[kB * kH];
__device__ float g_emb[kB * kEmb];
__device__ float g_mlp1[kB * kMlp];
__device__ __align__(16) float g_part[2 * kNCTA * kB * 64];   // per-layer planes
__device__ unsigned g_cnt0[kNTls], g_cnt1[kNTls];             // monotonic handoff
__device__ unsigned g_gen, g_barcnt;                          // 128-CTA barrier (init only)
__device__ unsigned g_gen64, g_bar64;                         // kz<2 barrier (publishes epi0)
__device__ unsigned g_gen64b, g_bar64b;                       // kz>=2 barrier (publishes epi1)
__device__ unsigned g_ep1done;                                // epi1 completion counter
__device__ __align__(16) float g_Y1[kM2 * kH];
__device__ __align__(16) float g_hid[kM2 * kHid];

__device__ __forceinline__ float sigm(float x) { return 1.f / (1.f + expf(-x)); }

__device__ __forceinline__ void split2(float e0, float e1, uint32_t& hi, uint32_t& lo) {
    float h0 = __bfloat162float(__float2bfloat16(e0));
    float h1 = __bfloat162float(__float2bfloat16(e1));
    asm("cvt.rn.bf16x2.f32 %0, %1, %2;" : "=r"(hi) : "f"(h1), "f"(h0));
    asm("cvt.rn.bf16x2.f32 %0, %1, %2;" : "=r"(lo) : "f"(e1 - h1), "f"(e0 - h0));
}

__device__ __forceinline__ void mma16(float c[4], const uint32_t a[4], uint32_t b0, uint32_t b1) {
    asm volatile("mma.sync.aligned.m16n8k16.row.col.f32.bf16.bf16.f32 "
                 "{%0,%1,%2,%3},{%4,%5,%6,%7},{%8,%9},{%0,%1,%2,%3};\n"
                 : "+f"(c[0]), "+f"(c[1]), "+f"(c[2]), "+f"(c[3])
                 : "r"(a[0]), "r"(a[1]), "r"(a[2]), "r"(a[3]), "r"(b0), "r"(b1));
}

__device__ __forceinline__ uint32_t s2u(const void* p) {
    return (uint32_t)__cvta_generic_to_shared(p);
}

__device__ __forceinline__ void bulk_ld(uint32_t sdst, const void* gsrc, uint32_t mbar) {
    asm volatile("mbarrier.arrive.expect_tx.shared.b64 _, [%0], %1;"
                 :: "r"(mbar), "r"(kBulkBytes) : "memory");
    asm volatile("cp.async.bulk.shared::cta.global.mbarrier::complete_tx::bytes "
                 "[%0], [%1], %2, [%3];"
                 :: "r"(sdst), "l"(gsrc), "r"(kBulkBytes), "r"(mbar) : "memory");
}

__device__ __forceinline__ void mbar_wait(uint32_t mbar, uint32_t parity) {
    uint32_t done;
    asm volatile(
        "{\n\t.reg .pred p;\n\t"
        "mbarrier.try_wait.parity.acquire.cta.shared::cta.b64 p, [%1], %2;\n\t"
        "selp.b32 %0, 1, 0, p;\n\t}"
        : "=r"(done) : "r"(mbar), "r"(parity) : "memory");
    if (!done) {
        asm volatile(
            "{\n\t.reg .pred P1;\n\t"
            "WL_%=:\n\t"
            "mbarrier.try_wait.parity.acquire.cta.shared::cta.b64 P1, [%0], %1, 0x989680;\n\t"
            "@P1 bra.uni WD_%=;\n\t"
            "bra.uni WL_%=;\n\t"
            "WD_%=:\n\t}"
            :: "r"(mbar), "r"(parity) : "memory");
    }
}

// full-grid barrier (128 CTAs) — used once after init
__device__ __forceinline__ void gridbar(unsigned& bt) {
    __threadfence();
    __syncthreads();
    if (threadIdx.x == 0) {
        unsigned arr = atomicAdd(&g_barcnt, 1u);
        if ((arr & (kNCTA - 1)) == kNCTA - 1) {
            asm volatile("st.release.gpu.global.u32 [%0], %1;" :: "l"(&g_gen), "r"(bt));
        } else {
            unsigned v;
            do { asm volatile("ld.acquire.gpu.global.u32 %0, [%1];" : "=r"(v) : "l"(&g_gen)); }
            while ((int)(v - bt) < 0);
        }
    }
    __syncthreads();
    bt++;
}

// 64-CTA barrier template over (cnt, gen)
__device__ __forceinline__ void bar64_of(unsigned* cnt, unsigned* gen, unsigned& bt) {
    __threadfence();
    __syncthreads();
    if (threadIdx.x == 0) {
        unsigned arr = atomicAdd(cnt, 1u);
        if ((arr & 63u) == 63u) {
            asm volatile("st.release.gpu.global.u32 [%0], %1;" :: "l"(gen), "r"(bt));
        } else {
            unsigned v;
            do { asm volatile("ld.acquire.gpu.global.u32 %0, [%1];" : "=r"(v) : "l"(gen)); }
            while ((int)(v - bt) < 0);
        }
    }
    __syncthreads();
    bt++;
}

__device__ __forceinline__ void spin_cnt(unsigned* p, unsigned tgt) {
    if (threadIdx.x == 0) {
        unsigned v;
        do { asm volatile("ld.acquire.gpu.global.u32 %0, [%1];" : "=r"(v) : "l"(p)); }
        while ((int)(v - tgt) < 0);
    }
    __syncthreads();
}

// ---------------- prep (EXACTLY 3 launches so lstm_persist = global launch #5) ----------------
__global__ void prepA(const float* __restrict__ sx, const float* __restrict__ w1,
                      const float* __restrict__ b1, const float* __restrict__ ew,
                      const float* __restrict__ eb) {
    int b = blockIdx.x, t = threadIdx.x;         // 192 threads
    if (t < kMlp) {
        float s = b1[t];
        #pragma unroll
        for (int d = 0; d < kStat; d++) s += sx[b * kStat + d] * w1[t * kStat + d];
        g_mlp1[b * kMlp + t] = fmaxf(s, 0.f);
    } else {
        int e = t - kMlp;
        float s = eb[e];
        #pragma unroll
        for (int d = 0; d < kStat; d++) s += sx[b * kStat + d] * ew[e * kStat + d];
        g_emb[b * kEmb + e] = fmaxf(s, 0.f);
    }
}

__global__ void prepB(const float* __restrict__ w2, const float* __restrict__ b2) {
    int b = blockIdx.x;
    int r = 2 * (blockIdx.y * 256 + threadIdx.x);
    float s0 = b2[r], s1 = b2[r + 1];
    #pragma unroll 4
    for (int m = 0; m < kMlp; m++) {
        float a = g_mlp1[b * kMlp + m];
        s0 += a * w2[r * kMlp + m];
        s1 += a * w2[(r + 1) * kMlp + m];
    }
    int ss = r >> 10, l = (r >> 9) & 1, h = r & 511;   // h even
    if (ss == 0) {
        uint32_t hi, lo; split2(s0, s1, hi, lo);
        if (l == 0) {
            int w = h >> 1;
            int o = ((w >> 6) * 2 + ((w >> 5) & 1)) * kSlice + b * 36 + (w & 31);
            g_a0[o] = hi; g_a0[o + 4608] = lo;
        } else {
            int w = 256 + (h >> 1);
            int o = ((w >> 7) * 4 + ((w >> 5) & 3)) * kSlice + b * 36 + (w & 31);
            g_a1[o] = hi; g_a1[o + 4608] = lo;
        }
    } else {
        if (l == 0) { g_c0[b * kH + h] = s0; g_c0[b * kH + h + 1] = s1; }
        else        { g_c1[b * kH + h] = s0; g_c1[b * kH + h + 1] = s1; }
    }
}

__global__ void prepC(const float* __restrict__ wih0, const float* __restrict__ bih0,
                      const float* __restrict__ bhh0, const float* __restrict__ bih1,
                      const float* __restrict__ bhh1) {
    int b = blockIdx.x;
    int n = blockIdx.y * 256 + threadIdx.x;
    int j = (n & 3) * kH + (n >> 2);
    float s = bih0[j] + bhh0[j];
    #pragma unroll 8
    for (int e = 0; e < kEmb; e++)
        s += g_emb[b * kEmb + e] * wih0[j * (kDdyn + kEmb) + kDdyn + e];
    g_pre0[b * kNG + n] = s;
    if (b == 0) g_pre1[n] = bih1[j] + bhh1[j];
}

// ---------------- one K=64 sub-slice of MMA work ----------------
template <int BSTR>
__device__ __forceinline__ void compute_sub(
    const uint32_t* __restrict__ Ah, const uint32_t* __restrict__ Al,
    const uint32_t* __restrict__ Bh, const uint32_t* __restrict__ Bl,
    int kbB, int wm, int wn, int g, int t4, float acc[2][4][4])
{
    #pragma unroll
    for (int s = 0; s < 4; s++) {
        int cw = s * 8;
        uint32_t ah[2][4], al[2][4];
        #pragma unroll
        for (int mf = 0; mf < 2; mf++) {
            int r0 = (wm * 32 + mf * 16 + g) * 36 + cw;
            int r1 = r0 + 8 * 36;
            ah[mf][0] = Ah[r0 + t4];     ah[mf][1] = Ah[r1 + t4];
            ah[mf][2] = Ah[r0 + 4 + t4]; ah[mf][3] = Ah[r1 + 4 + t4];
            al[mf][0] = Al[r0 + t4];     al[mf][1] = Al[r1 + t4];
            al[mf][2] = Al[r0 + 4 + t4]; al[mf][3] = Al[r1 + 4 + t4];
        }
        #pragma unroll
        for (int nf = 0; nf < 4; nf++) {
            int base = (wn * 32 + nf * 8 + g) * BSTR + kbB + cw;
            uint32_t bh0 = Bh[base + t4], bh1 = Bh[base + 4 + t4];
            uint32_t bl0 = Bl[base + t4], bl1 = Bl[base + 4 + t4];
            #pragma unroll
            for (int mf = 0; mf < 2; mf++) {
                mma16(acc[mf][nf], ah[mf], bh0, bh1);
                mma16(acc[mf][nf], ah[mf], bl0, bl1);
                mma16(acc[mf][nf], al[mf], bh0, bh1);
            }
        }
    }
}

// ---------------- half-epilogue: 128 rows x 32 cols ----------------
template <int L>
__device__ __forceinline__ void epilogue_half(int par, int step, int ntile, int n0, int half,
                                              int tid, const float* sWd,
                                              const float* __restrict__ ctx,
                                              const float* __restrict__ fut) {
    int m = tid >> 1;
    int nh = half * 32 + (tid & 1) * 16;
    float s[16];
    #pragma unroll
    for (int j = 0; j < 16; j++) s[j] = 0.f;
    #pragma unroll 1
    for (int z = 0; z < 4; z++) {                      // fixed order -> deterministic
        const float4* q = reinterpret_cast<const float4*>(
            g_part + (size_t)(L * kNCTA + ntile * 4 + z) * (kB * 64) + m * 64 + nh);
        #pragma unroll
        for (int j = 0; j < 4; j++) {
            float4 v = __ldcg(q + j);
            s[j*4] += v.x; s[j*4+1] += v.y; s[j*4+2] += v.z; s[j*4+3] += v.w;
        }
    }
    if (L == 0) {                                      // dynamic-x term
        const float* xp = (step < kCtx)
            ? ctx + (size_t)m * (kCtx * kDdyn) + step * kDdyn
            : fut + (size_t)m * (kPred * kDdyn) + (step - kCtx) * kDdyn;
        #pragma unroll
        for (int d = 0; d < kDdyn; d++) {
            float xv = __ldg(xp + d);
            const float4* w4 = (const float4*)(sWd + d * 64 + nh);
            #pragma unroll
            for (int q = 0; q < 4; q++) {
                float4 w = w4[q];
                s[q*4]   += xv * w.x; s[q*4+1] += xv * w.y;
                s[q*4+2] += xv * w.z; s[q*4+3] += xv * w.w;
            }
        }
    }
    const float* pre = (L == 0) ? &g_pre0[m * kNG + n0 + nh] : &g_pre1[n0 + nh];
    float* cst = (L == 0) ? g_c0 : g_c1;
    float hv[4];
    #pragma unroll
    for (int j = 0; j < 16; j += 4) {
        int u = (n0 + nh + j) >> 2;
        float gi = s[j] + pre[j], gf = s[j+1] + pre[j+1];
        float gg = s[j+2] + pre[j+2], go = s[j+3] + pre[j+3];
        float iv = sigm(gi), fv = sigm(gf), gv = tanhf(gg), ov = sigm(go);
        float c = fv * cst[m * kH + u] + iv * gv;      // c-state is CTA-private (static performer)
        cst[m * kH + u] = c;
        hv[j >> 2] = ov * tanhf(c);
    }
    int wb = (n0 + nh) >> 3;
    if (L == 0) {
        uint32_t* a0 = g_a0 + (size_t)(par ^ 1) * kA0Buf;   // next-step h0
        uint32_t* a1 = g_a1 + (size_t)par * kA1Buf;         // y0 for this step's L1
        #pragma unroll
        for (int p = 0; p < 2; p++) {
            int w = wb + p;
            uint32_t hi, lo; split2(hv[2*p], hv[2*p+1], hi, lo);
            int o0 = ((w >> 6) * 2 + ((w >> 5) & 1)) * kSlice + m * 36 + (w & 31);
            a0[o0] = hi; a0[o0 + 4608] = lo;
            int o1 = ((w >> 7) * 4 + ((w >> 5) & 3)) * kSlice + m * 36 + (w & 31);
            a1[o1] = hi; a1[o1 + 4608] = lo;
        }
    } else {
        uint32_t* a1 = g_a1 + (size_t)(par ^ 1) * kA1Buf;   // next-step h1
        #pragma unroll
        for (int p = 0; p < 2; p++) {
            int w = 256 + wb + p;
            uint32_t hi, lo; split2(hv[2*p], hv[2*p+1], hi, lo);
            int o = ((w >> 7) * 4 + ((w >> 5) & 3)) * kSlice + m * 36 + (w & 31);
            a1[o] = hi; a1[o + 4608] = lo;
        }
        int trow = step - kCtx;
        if (trow >= 0) {
            int u0 = (n0 + nh) >> 2;
            #pragma unroll
            for (int p = 0; p < 4; p++)
                g_Y1[(size_t)(trow * kB + m) * kH + u0 + p] = hv[p];
        }
    }
}

// ---------------- persistent kernel ----------------
__global__ void __launch_bounds__(256, 1) lstm_persist(
    const float* __restrict__ ctx, const float* __restrict__ fut,
    const float* __restrict__ whh0, const float* __restrict__ wih0,
    const float* __restrict__ wih1, const float* __restrict__ whh1)
{
    extern __shared__ __align__(16) uint32_t smu[];
    uint32_t* sW0h = smu + oW0h; uint32_t* sW0l = smu + oW0l;
    uint32_t* sW1h = smu + oW1h; uint32_t* sW1l = smu + oW1l;
    float* sWd = (float*)(smu + oWd);
    uint32_t* rsH[2] = { smu + oRing, smu + oRing + 9216 };
    uint32_t* rsL[2] = { smu + oRing + 4608, smu + oRing + 13824 };
    __shared__ __align__(8) unsigned long long sMbar[2];

    const int tid = threadIdx.x, cta = blockIdx.x;
    const int ntile = cta >> 2, kz = cta & 3, n0 = ntile * 64;

    // monotonic bases (read BEFORE the initial full barrier -> replay-safe)
    unsigned bt    = *((volatile unsigned*)&g_gen) + 1;
    unsigned bt64  = *((volatile unsigned*)&g_gen64) + 1;
    unsigned bt64b = *((volatile unsigned*)&g_gen64b) + 1;
    unsigned g64b  = bt64 - 1;
    unsigned c0b   = *((volatile unsigned*)&g_cnt0[ntile]);
    unsigned c1b   = *((volatile unsigned*)&g_cnt1[ntile]);
    unsigned e1b   = *((volatile unsigned*)&g_ep1done);

    // weight slices -> SMEM (bf16 hi/lo pairs, interleaved gate rows)
    for (int idx = tid; idx < 64 * 64; idx += 256) {
        int nl = idx >> 6, kw = idx & 63;
        int n = n0 + nl, j = (n & 3) * kH + (n >> 2);
        int k0 = kz * 128 + 2 * kw;
        uint32_t hi, lo;
        split2(whh0[j * kH + k0], whh0[j * kH + k0 + 1], hi, lo);
        sW0h[nl * 68 + kw] = hi; sW0l[nl * 68 + kw] = lo;
    }
    for (int idx = tid; idx < 64 * 128; idx += 256) {
        int nl = idx >> 7, kw = idx & 127;
        int n = n0 + nl, j = (n & 3) * kH + (n >> 2);
        int k0 = kz * 256 + 2 * kw, k1 = k0 + 1;
        float v0 = (k0 < kH) ? wih1[j * kH + k0] : whh1[j * kH + k0 - kH];
        float v1 = (k1 < kH) ? wih1[j * kH + k1] : whh1[j * kH + k1 - kH];
        uint32_t hi, lo; split2(v0, v1, hi, lo);
        sW1h[nl * 132 + kw] = hi; sW1l[nl * 132 + kw] = lo;
    }
    for (int idx = tid; idx < kDdyn * 64; idx += 256) {
        int d = idx >> 6, nl = idx & 63;
        int n = n0 + nl, j = (n & 3) * kH + (n >> 2);
        sWd[d * 64 + nl] = wih0[j * (kDdyn + kEmb) + d];
    }
    if (tid == 0) {
        asm volatile("mbarrier.init.shared.b64 [%0], 1;" :: "r"(s2u(&sMbar[0])) : "memory");
        asm volatile("mbarrier.init.shared.b64 [%0], 1;" :: "r"(s2u(&sMbar[1])) : "memory");
    }
    __syncthreads();
    gridbar(bt);   // bases read + weights staged before any counter bumps

    const uint32_t mb0 = s2u(&sMbar[0]), mb1 = s2u(&sMbar[1]);
    const uint32_t rd0 = s2u(rsH[0]), rd1 = s2u(rsH[1]);
    const int w = tid >> 5, lane = tid & 31;
    const int wm = w & 3, wn = w >> 2;
    const int g = lane >> 2, t4 = lane & 3;
    float* pp0 = g_part + (size_t)cta * (kB * 64);
    float* pp1 = g_part + (size_t)(kNCTA + cta) * (kB * 64);
    unsigned p0 = 0, p1 = 0;

    #pragma unroll 1
    for (int step = 0; step < kT; step++) {
        const int par = step & 1;
        // ===== layer 0 GEMM (all CTAs) =====
        {
            // kz>=2: wait for epi0(step-1) published via bar64 release (also guards
            // plane-0 partials reuse). kz<2 passed bar64(step-1) themselves.
            if (kz >= 2 && step > 0) spin_cnt(&g_gen64, g64b + (unsigned)step);
            const uint32_t* src = g_a0 + (size_t)par * kA0Buf + (kz * 2) * kSlice;
            if (tid == 0) { bulk_ld(rd0, src, mb0); bulk_ld(rd1, src + kSlice, mb1); }
            float acc[2][4][4];
            #pragma unroll
            for (int a = 0; a < 2; a++)
                #pragma unroll
                for (int b = 0; b < 4; b++)
                    #pragma unroll
                    for (int c = 0; c < 4; c++) acc[a][b][c] = 0.f;
            mbar_wait(mb0, p0); p0 ^= 1;
            compute_sub<68>(rsH[0], rsL[0], sW0h, sW0l, 0, wm, wn, g, t4, acc);
            mbar_wait(mb1, p1); p1 ^= 1;
            compute_sub<68>(rsH[1], rsL[1], sW0h, sW0l, 32, wm, wn, g, t4, acc);
            #pragma unroll
            for (int mf = 0; mf < 2; mf++)
                #pragma unroll
                for (int nf = 0; nf < 4; nf++) {
                    int row = wm * 32 + mf * 16 + g, col = wn * 32 + nf * 8 + t4 * 2;
                    *(float2*)&pp0[row * 64 + col]       = make_float2(acc[mf][nf][0], acc[mf][nf][1]);
                    *(float2*)&pp0[(row + 8) * 64 + col] = make_float2(acc[mf][nf][2], acc[mf][nf][3]);
                }
            __threadfence();
            __syncthreads();
            if (tid == 0) atomicAdd(&g_cnt0[ntile], 1u);
        }
        if (kz < 2) {
            // ===== epi0 + publish, then L1 on y0 =====
            spin_cnt(&g_cnt0[ntile], c0b + 4u * (unsigned)(step + 1));
            epilogue_half<0>(par, step, ntile, n0, kz, tid, sWd, ctx, fut);
            bar64_of(&g_bar64, &g_gen64, bt64);        // epi0 done chip-wide -> y0 readable
            const uint32_t* src = g_a1 + (size_t)par * kA1Buf + (kz * 4) * kSlice;
            if (tid == 0) { bulk_ld(rd0, src, mb0); bulk_ld(rd1, src + kSlice, mb1); }
            float acc[2][4][4];
            #pragma unroll
            for (int a = 0; a < 2; a++)
                #pragma unroll
                for (int b = 0; b < 4; b++)
                    #pragma unroll
                    for (int c = 0; c < 4; c++) acc[a][b][c] = 0.f;
            mbar_wait(mb0, p0); p0 ^= 1;
            compute_sub<132>(rsH[0], rsL[0], sW1h, sW1l, 0, wm, wn, g, t4, acc);
            __syncthreads();
            if (tid == 0) bulk_ld(rd0, src + 2 * kSlice, mb0);
            mbar_wait(mb1, p1); p1 ^= 1;
            compute_sub<132>(rsH[1], rsL[1], sW1h, sW1l, 32, wm, wn, g, t4, acc);
            __syncthreads();
            if (tid == 0) bulk_ld(rd1, src + 3 * kSlice, mb1);
            mbar_wait(mb0, p0); p0 ^= 1;
            compute_sub<132>(rsH[0], rsL[0], sW1h, sW1l, 64, wm, wn, g, t4, acc);
            mbar_wait(mb1, p1); p1 ^= 1;
            compute_sub<132>(rsH[1], rsL[1], sW1h, sW1l, 96, wm, wn, g, t4, acc);
            // before overwriting plane-1 partials: epi1(step-1) readers must be done
            if (step > 0) spin_cnt(&g_ep1done, e1b + 64u * (unsigned)step);
            #pragma unroll
            for (int mf = 0; mf < 2; mf++)
                #pragma unroll
                for (int nf = 0; nf < 4; nf++) {
                    int row = wm * 32 + mf * 16 + g, col = wn * 32 + nf * 8 + t4 * 2;
                    *(float2*)&pp1[row * 64 + col]       = make_float2(acc[mf][nf][0], acc[mf][nf][1]);
                    *(float2*)&pp1[(row + 8) * 64 + col] = make_float2(acc[mf][nf][2], acc[mf][nf][3]);
                }
            __threadfence();
            __syncthreads();
            if (tid == 0) atomicAdd(&g_cnt1[ntile], 1u);
            // proceed straight to next step's L0 (no wait on epi1)
        } else {
            // ===== L1 on h1 (ready since bar64b(step-1)), then epi1 + publish =====
            const uint32_t* src = g_a1 + (size_t)par * kA1Buf + (kz * 4) * kSlice;
            if (tid == 0) { bulk_ld(rd0, src, mb0); bulk_ld(rd1, src + kSlice, mb1); }
            float acc[2][4][4];
            #pragma unroll
            for (int a = 0; a < 2; a++)
                #pragma unroll
                for (int b = 0; b < 4; b++)
                    #pragma unroll
                    for (int c = 0; c < 4; c++) acc[a][b][c] = 0.f;
            mbar_wait(mb0, p0); p0 ^= 1;
            compute_sub<132>(rsH[0], rsL[0], sW1h, sW1l, 0, wm, wn, g, t4, acc);
            __syncthreads();
            if (tid == 0) bulk_ld(rd0, src + 2 * kSlice, mb0);
            mbar_wait(mb1, p1); p1 ^= 1;
            compute_sub<132>(rsH[1], rsL[1], sW1h, sW1l, 32, wm, wn, g, t4, acc);
            __syncthreads();
            if (tid == 0) bulk_ld(rd1, src + 3 * kSlice, mb1);
            mbar_wait(mb0, p0); p0 ^= 1;
            compute_sub<132>(rsH[0], rsL[0], sW1h, sW1l, 64, wm, wn, g, t4, acc);
            mbar_wait(mb1, p1); p1 ^= 1;
            compute_sub<132>(rsH[1], rsL[1], sW1h, sW1l, 96, wm, wn, g, t4, acc);
            #pragma unroll
            for (int mf = 0; mf < 2; mf++)
                #pragma unroll
                for (int nf = 0; nf < 4; nf++) {
                    int row = wm * 32 + mf * 16 + g, col = wn * 32 + nf * 8 + t4 * 2;
                    *(float2*)&pp1[row * 64 + col]       = make_float2(acc[mf][nf][0], acc[mf][nf][1]);
                    *(float2*)&pp1[(row + 8) * 64 + col] = make_float2(acc[mf][nf][2], acc[mf][nf][3]);
                }
            __threadfence();
            __syncthreads();
            if (tid == 0) atomicAdd(&g_cnt1[ntile], 1u);
            spin_cnt(&g_cnt1[ntile], c1b + 4u * (unsigned)(step + 1));
            epilogue_half<1>(par, step, ntile, n0, kz - 2, tid, sWd, ctx, fut);
            __threadfence();
            __syncthreads();
            if (tid == 0) atomicAdd(&g_ep1done, 1u);
            bar64_of(&g_bar64b, &g_gen64b, bt64b);     // epi1 done among kz>=2 -> h1 readable
        }
    }
}

// ---------------- head GEMMs ----------------
__global__ void __launch_bounds__(128) head1_gemm(const float* __restrict__ w1,
                                                  const float* __restrict__ b1) {
    __shared__ __align__(16) float As[2][16 * 68];
    __shared__ __align__(16) float Bs[2][16 * 36];
    const int tid = threadIdx.x;
    const int m0 = blockIdx.x * 64, n0 = blockIdx.y * 32;
    const int tm = tid & 15, tn = tid >> 4;
    constexpr int NT = kH / 16;
    float acc[4][4];
    #pragma unroll
    for (int i = 0; i < 4; i++)
        #pragma unroll
        for (int j = 0; j < 4; j++) acc[i][j] = 0.f;
    float ar[8]; float4 br;
    auto loadA = [&](int k0) {
        #pragma unroll
        for (int i = 0; i < 2; i++) {
            int li = tid * 2 + i, bb = li >> 2, kf = li & 3;
            float4 v = *reinterpret_cast<const float4*>(&g_Y1[(m0 + bb) * kH + k0 + kf * 4]);
            ar[i*4] = v.x; ar[i*4+1] = v.y; ar[i*4+2] = v.z; ar[i*4+3] = v.w;
        }
    };
    auto storeA = [&](int buf) {
        #pragma unroll
        for (int i = 0; i < 2; i++) {
            int li = tid * 2 + i, bb = li >> 2, kf = li & 3;
            #pragma unroll
            for (int j = 0; j < 4; j++) As[buf][(kf * 4 + j) * 68 + bb] = ar[i * 4 + j];
        }
    };
    auto loadB = [&](int k0) {
        int n = tid >> 2, kf = tid & 3;
        br = *reinterpret_cast<const float4*>(&w1[(n0 + n) * kH + k0 + kf * 4]);
    };
    auto storeB = [&](int buf) {
        int n = tid >> 2, kf = tid & 3;
        Bs[buf][(kf*4+0)*36+n] = br.x; Bs[buf][(kf*4+1)*36+n] = br.y;
        Bs[buf][(kf*4+2)*36+n] = br.z; Bs[buf][(kf*4+3)*36+n] = br.w;
    };
    loadA(0); loadB(0); storeA(0); storeB(0);
    __syncthreads();
    for (int kt = 0; kt < NT; ++kt) {
        int cur = kt & 1;
        if (kt + 1 < NT) { loadA((kt + 1) * 16); loadB((kt + 1) * 16); }
        #pragma unroll
        for (int kk = 0; kk < 16; ++kk) {
            float4 av = *reinterpret_cast<const float4*>(&As[cur][kk * 68 + tm * 4]);
            float4 bv = *reinterpret_cast<const float4*>(&Bs[cur][kk * 36 + tn * 4]);
            acc[0][0]+=av.x*bv.x; acc[0][1]+=av.x*bv.y; acc[0][2]+=av.x*bv.z; acc[0][3]+=av.x*bv.w;
            acc[1][0]+=av.y*bv.x; acc[1][1]+=av.y*bv.y; acc[1][2]+=av.y*bv.z; acc[1][3]+=av.y*bv.w;
            acc[2][0]+=av.z*bv.x; acc[2][1]+=av.z*bv.y; acc[2][2]+=av.z*bv.z; acc[2][3]+=av.z*bv.w;
            acc[3][0]+=av.w*bv.x; acc[3][1]+=av.w*bv.y; acc[3][2]+=av.w*bv.z; acc[3][3]+=av.w*bv.w;
        }
        if (kt + 1 < NT) { storeA(cur ^ 1); storeB(cur ^ 1); }
        __syncthreads();
    }
    #pragma unroll
    for (int i = 0; i < 4; i++) {
        int mg = m0 + tm * 4 + i;
        #pragma unroll
        for (int j = 0; j < 4; j++) {
            int ng = n0 + tn * 4 + j;
            g_hid[mg * kHid + ng] = fmaxf(acc[i][j] + b1[ng], 0.f);
        }
    }
}

__global__ void head2_kernel(const float* __restrict__ w2, const float* __restrict__ b2,
                             float* __restrict__ out) {
    int idx = blockIdx.x * 256 + threadIdx.x;
    int m = idx >> 2, o = idx & 3;
    const float4* hp = reinterpret_cast<const float4*>(g_hid + m * kHid);
    const float4* wp = reinterpret_cast<const float4*>(w2 + o * kHid);
    float s = 0.f;
    #pragma unroll 8
    for (int k = 0; k < kHid / 4; k++) {
        float4 a = hp[k], b = wp[k];
        s += a.x * b.x + a.y * b.y + a.z * b.z + a.w * b.w;
    }
    s += b2[o];
    int bb = m & (kB - 1), t = m >> 7;
    out[bb * (kPred * kOut) + t * kOut + o] = s;
}

extern "C" void kernel_launch(void* const* d_in, const int* in_sizes, int n_in,
                              void* d_out, int out_size) {
    const float* ctx   = (const float*)d_in[0];
    const float* sx    = (const float*)d_in[1];
    const float* fut   = (const float*)d_in[2];
    const float* mlpw1 = (const float*)d_in[3];
    const float* mlpb1 = (const float*)d_in[4];
    const float* mlpw2 = (const float*)d_in[5];
    const float* mlpb2 = (const float*)d_in[6];
    const float* embw  = (const float*)d_in[7];
    const float* embb  = (const float*)d_in[8];
    const float* wih0  = (const float*)d_in[9];
    const float* whh0  = (const float*)d_in[10];
    const float* bih0  = (const float*)d_in[11];
    const float* bhh0  = (const float*)d_in[12];
    const float* wih1  = (const float*)d_in[13];
    const float* whh1  = (const float*)d_in[14];
    const float* bih1  = (const float*)d_in[15];
    const float* bhh1  = (const float*)d_in[16];
    const float* hw1   = (const float*)d_in[17];
    const float* hb1   = (const float*)d_in[18];
    const float* hw2   = (const float*)d_in[19];
    const float* hb2   = (const float*)d_in[20];
    float* out = (float*)d_out;

    // exactly 3 preps -> lstm_persist stays at global launch #5 for ncu
    prepA<<<kB, 192>>>(sx, mlpw1, mlpb1, embw, embb);
    prepB<<<dim3(kB, 4), 256>>>(mlpw2, mlpb2);
    prepC<<<dim3(kB, 8), 256>>>(wih0, bih0, bhh0, bih1, bhh1);

    cudaFuncSetAttribute(lstm_persist, cudaFuncAttributeMaxDynamicSharedMemorySize, kSmemBytes);
    lstm_persist<<<kNCTA, 256, kSmemBytes>>>(ctx, fut, whh0, wih0, wih1, whh1);

    head1_gemm<<<dim3(kM2 / 64, kHid / 32), 128>>>(hw1, hb1);
    head2_kernel<<<kM2 * kOut / 256, 256>>>(hw2, hb2, out);
}